// round 2
// baseline (speedup 1.0000x reference)
#include <cuda_runtime.h>
#include <cuda_bf16.h>

#define N_NODES 25000
#define N_EDGES 400000
#define F_IN    128
#define D_ATTR  16
#define H_DIM   64
#define HID     128
#define OUT_DIM 32
#define G_GRAPHS 64

// ---------------- scratch (device globals: no allocation allowed) -----------
__device__ float g_a[N_NODES * H_DIM];
__device__ float g_b[N_NODES * H_DIM];
__device__ float g_eagg[N_NODES * H_DIM];
__device__ float g_cusum[N_NODES * 3];
__device__ float g_deg[N_NODES];
__device__ float g_x1[N_NODES * HID];
__device__ float g_x2[N_NODES * HID];
__device__ float g_pos1[N_NODES * 3];
__device__ float g_gsum[G_GRAPHS * HID];
__device__ float g_gcnt[G_GRAPHS];

__device__ __forceinline__ float silu_f(float v) {
    return v / (1.0f + __expf(-v));
}

// ---------------- zero kernels ----------------------------------------------
__global__ void zero_edge_acc(float* eagg, float* cusum, float* deg) {
    int i = blockIdx.x * blockDim.x + threadIdx.x;
    int T = gridDim.x * blockDim.x;
    for (int j = i; j < N_NODES * H_DIM; j += T) eagg[j] = 0.f;
    for (int j = i; j < N_NODES * 3; j += T) cusum[j] = 0.f;
    for (int j = i; j < N_NODES; j += T) deg[j] = 0.f;
}

__global__ void zero_pool(float* gsum, float* gcnt) {
    int i = blockIdx.x * blockDim.x + threadIdx.x;
    if (i < G_GRAPHS * HID) gsum[i] = 0.f;
    if (i < G_GRAPHS) gcnt[i] = 0.f;
}

// ---------------- per-node precompute: a = x@W_dst, b = x@W_src -------------
// mlp_w is (273, 64) row-major. rows [0,128)=W_dst, [128,256)=W_src,
// [256,272)=W_attr, row 272 = w_radial.
__global__ void precompute_ab(const float* __restrict__ x,
                              const float* __restrict__ mlp_w,
                              float* __restrict__ a, float* __restrict__ b) {
    extern __shared__ float sw[];         // 2 * 128*64 floats = 64KB
    float* s_wd = sw;
    float* s_ws = sw + F_IN * H_DIM;
    for (int i = threadIdx.x; i < F_IN * H_DIM; i += blockDim.x) {
        s_wd[i] = mlp_w[i];
        s_ws[i] = mlp_w[F_IN * H_DIM + i];
    }
    __syncthreads();

    int gtid = blockIdx.x * blockDim.x + threadIdx.x;
    int warp = gtid >> 5;
    int lane = threadIdx.x & 31;
    int nwarps = (gridDim.x * blockDim.x) >> 5;
    int k0 = lane * 2;

    for (int node = warp; node < N_NODES; node += nwarps) {
        const float4* xr = (const float4*)(x + (size_t)node * F_IN);
        float a0 = 0.f, a1 = 0.f, b0 = 0.f, b1 = 0.f;
#pragma unroll 8
        for (int q = 0; q < 32; q++) {
            float4 xv = xr[q];
            int j = 4 * q;
            float2 w;
            w = *(const float2*)(s_wd + (j + 0) * H_DIM + k0); a0 += xv.x * w.x; a1 += xv.x * w.y;
            w = *(const float2*)(s_wd + (j + 1) * H_DIM + k0); a0 += xv.y * w.x; a1 += xv.y * w.y;
            w = *(const float2*)(s_wd + (j + 2) * H_DIM + k0); a0 += xv.z * w.x; a1 += xv.z * w.y;
            w = *(const float2*)(s_wd + (j + 3) * H_DIM + k0); a0 += xv.w * w.x; a1 += xv.w * w.y;
            w = *(const float2*)(s_ws + (j + 0) * H_DIM + k0); b0 += xv.x * w.x; b1 += xv.x * w.y;
            w = *(const float2*)(s_ws + (j + 1) * H_DIM + k0); b0 += xv.y * w.x; b1 += xv.y * w.y;
            w = *(const float2*)(s_ws + (j + 2) * H_DIM + k0); b0 += xv.z * w.x; b1 += xv.z * w.y;
            w = *(const float2*)(s_ws + (j + 3) * H_DIM + k0); b0 += xv.w * w.x; b1 += xv.w * w.y;
        }
        *(float2*)(a + (size_t)node * H_DIM + k0) = make_float2(a0, a1);
        *(float2*)(b + (size_t)node * H_DIM + k0) = make_float2(b0, b1);
    }
}

// ---------------- edge kernel: warp per edge ---------------------------------
__global__ void edge_kernel(const float* __restrict__ pos,
                            const int* __restrict__ eidx,
                            const float* __restrict__ edge_attr,
                            const float* __restrict__ mlp_w,
                            const float* __restrict__ edge_w,
                            const float* __restrict__ edge_b,
                            const float* __restrict__ coord_w,
                            const float* __restrict__ coord_b,
                            const float* __restrict__ a,
                            const float* __restrict__ b,
                            float* __restrict__ eagg,
                            float* __restrict__ cusum,
                            float* __restrict__ deg) {
    __shared__ float s_wattr[D_ATTR * H_DIM];   // 4KB
    __shared__ float s_wrad[H_DIM];
    __shared__ float s_ew[H_DIM * H_DIM];       // 16KB
    __shared__ float s_eb[H_DIM];
    __shared__ float s_cw[H_DIM];
    __shared__ float s_cb;

    for (int i = threadIdx.x; i < D_ATTR * H_DIM; i += blockDim.x)
        s_wattr[i] = mlp_w[(2 * F_IN) * H_DIM + i];
    for (int i = threadIdx.x; i < H_DIM * H_DIM; i += blockDim.x)
        s_ew[i] = edge_w[i];
    if (threadIdx.x < H_DIM) {
        s_wrad[threadIdx.x] = mlp_w[(2 * F_IN + D_ATTR) * H_DIM + threadIdx.x];
        s_eb[threadIdx.x] = edge_b[threadIdx.x];
        s_cw[threadIdx.x] = coord_w[threadIdx.x];
    }
    if (threadIdx.x == 0) s_cb = coord_b[0];
    __syncthreads();

    int gtid = blockIdx.x * blockDim.x + threadIdx.x;
    int warp = gtid >> 5;
    int lane = threadIdx.x & 31;
    int nwarps = (gridDim.x * blockDim.x) >> 5;
    int k0 = lane * 2;

    for (int e = warp; e < N_EDGES; e += nwarps) {
        int src = eidx[e];
        int dst = eidx[N_EDGES + e];

        float dx = pos[dst * 3 + 0] - pos[src * 3 + 0];
        float dy = pos[dst * 3 + 1] - pos[src * 3 + 1];
        float dz = pos[dst * 3 + 2] - pos[src * 3 + 2];
        float radial = dx * dx + dy * dy + dz * dz;

        float2 av = *(const float2*)(a + (size_t)dst * H_DIM + k0);
        float2 bv = *(const float2*)(b + (size_t)src * H_DIM + k0);
        float h0 = av.x + bv.x + radial * s_wrad[k0];
        float h1 = av.y + bv.y + radial * s_wrad[k0 + 1];

        const float4* eat = (const float4*)(edge_attr + (size_t)e * D_ATTR);
#pragma unroll
        for (int q = 0; q < 4; q++) {
            float4 ev = eat[q];
            int d = 4 * q;
            float2 w;
            w = *(const float2*)(s_wattr + (d + 0) * H_DIM + k0); h0 += ev.x * w.x; h1 += ev.x * w.y;
            w = *(const float2*)(s_wattr + (d + 1) * H_DIM + k0); h0 += ev.y * w.x; h1 += ev.y * w.y;
            w = *(const float2*)(s_wattr + (d + 2) * H_DIM + k0); h0 += ev.z * w.x; h1 += ev.z * w.y;
            w = *(const float2*)(s_wattr + (d + 3) * H_DIM + k0); h0 += ev.w * w.x; h1 += ev.w * w.y;
        }
        h0 = silu_f(h0);
        h1 = silu_f(h1);

        // e = silu(h @ edge_w + eb); lane owns columns k0, k0+1.
        // h is lane-distributed: lane l holds h[2l], h[2l+1].
        float e0a = s_eb[k0], e1a = s_eb[k0 + 1];
        float e0b = 0.f, e1b = 0.f;
#pragma unroll
        for (int jj = 0; jj < 32; jj++) {
            float hA = __shfl_sync(0xffffffffu, h0, jj);   // h[2*jj]
            float hB = __shfl_sync(0xffffffffu, h1, jj);   // h[2*jj+1]
            float2 wA = *(const float2*)(s_ew + (2 * jj) * H_DIM + k0);
            float2 wB = *(const float2*)(s_ew + (2 * jj + 1) * H_DIM + k0);
            e0a += hA * wA.x; e1a += hA * wA.y;
            e0b += hB * wB.x; e1b += hB * wB.y;
        }
        float e0 = silu_f(e0a + e0b);
        float e1 = silu_f(e1a + e1b);

        // coordinate scalar
        float part = e0 * s_cw[k0] + e1 * s_cw[k0 + 1];
#pragma unroll
        for (int off = 16; off; off >>= 1)
            part += __shfl_xor_sync(0xffffffffu, part, off);
        float s = silu_f(part + s_cb);

        atomicAdd(eagg + (size_t)dst * H_DIM + k0, e0);
        atomicAdd(eagg + (size_t)dst * H_DIM + k0 + 1, e1);
        if (lane == 0) {
            atomicAdd(cusum + dst * 3 + 0, dx * s);
            atomicAdd(cusum + dst * 3 + 1, dy * s);
            atomicAdd(cusum + dst * 3 + 2, dz * s);
            atomicAdd(deg + dst, 1.0f);
        }
    }
}

// ---------------- node kernel: warp per node ---------------------------------
__global__ void node_kernel(const float* __restrict__ xin,
                            const float* __restrict__ posin,
                            const float* __restrict__ eagg,
                            const float* __restrict__ cusum,
                            const float* __restrict__ deg,
                            const float* __restrict__ nw1,
                            const float* __restrict__ nb1,
                            const float* __restrict__ nw2,
                            const float* __restrict__ nb2,
                            float* __restrict__ xout,
                            float* __restrict__ posout) {
    extern __shared__ float sm[];
    float* s_w1 = sm;                              // 192*64
    float* s_w2 = s_w1 + (F_IN + H_DIM) * H_DIM;   // 64*128
    float* s_b1 = s_w2 + H_DIM * HID;              // 64
    float* s_b2 = s_b1 + H_DIM;                    // 128

    for (int i = threadIdx.x; i < (F_IN + H_DIM) * H_DIM; i += blockDim.x) s_w1[i] = nw1[i];
    for (int i = threadIdx.x; i < H_DIM * HID; i += blockDim.x) s_w2[i] = nw2[i];
    if (threadIdx.x < H_DIM) s_b1[threadIdx.x] = nb1[threadIdx.x];
    if (threadIdx.x < HID) s_b2[threadIdx.x] = nb2[threadIdx.x];
    __syncthreads();

    int gtid = blockIdx.x * blockDim.x + threadIdx.x;
    int warp = gtid >> 5;
    int lane = threadIdx.x & 31;
    int nwarps = (gridDim.x * blockDim.x) >> 5;
    int k0 = lane * 2;

    for (int node = warp; node < N_NODES; node += nwarps) {
        float t0 = s_b1[k0], t1 = s_b1[k0 + 1];
        const float4* xr = (const float4*)(xin + (size_t)node * F_IN);
#pragma unroll 8
        for (int q = 0; q < 32; q++) {
            float4 xv = xr[q];
            int j = 4 * q;
            float2 w;
            w = *(const float2*)(s_w1 + (j + 0) * H_DIM + k0); t0 += xv.x * w.x; t1 += xv.x * w.y;
            w = *(const float2*)(s_w1 + (j + 1) * H_DIM + k0); t0 += xv.y * w.x; t1 += xv.y * w.y;
            w = *(const float2*)(s_w1 + (j + 2) * H_DIM + k0); t0 += xv.z * w.x; t1 += xv.z * w.y;
            w = *(const float2*)(s_w1 + (j + 3) * H_DIM + k0); t0 += xv.w * w.x; t1 += xv.w * w.y;
        }
        const float4* er = (const float4*)(eagg + (size_t)node * H_DIM);
#pragma unroll 8
        for (int q = 0; q < 16; q++) {
            float4 ev = er[q];
            int j = F_IN + 4 * q;
            float2 w;
            w = *(const float2*)(s_w1 + (j + 0) * H_DIM + k0); t0 += ev.x * w.x; t1 += ev.x * w.y;
            w = *(const float2*)(s_w1 + (j + 1) * H_DIM + k0); t0 += ev.y * w.x; t1 += ev.y * w.y;
            w = *(const float2*)(s_w1 + (j + 2) * H_DIM + k0); t0 += ev.z * w.x; t1 += ev.z * w.y;
            w = *(const float2*)(s_w1 + (j + 3) * H_DIM + k0); t0 += ev.w * w.x; t1 += ev.w * w.y;
        }
        t0 = silu_f(t0);
        t1 = silu_f(t1);

        // xout = t @ nw2 + b2 ; lane owns 4 output columns [4*lane, 4*lane+4)
        float4 acc = *(const float4*)(s_b2 + 4 * lane);
#pragma unroll
        for (int jj = 0; jj < 32; jj++) {
            float tA = __shfl_sync(0xffffffffu, t0, jj);   // t[2*jj]
            float tB = __shfl_sync(0xffffffffu, t1, jj);   // t[2*jj+1]
            float4 wA = *(const float4*)(s_w2 + (2 * jj) * HID + 4 * lane);
            float4 wB = *(const float4*)(s_w2 + (2 * jj + 1) * HID + 4 * lane);
            acc.x += tA * wA.x + tB * wB.x;
            acc.y += tA * wA.y + tB * wB.y;
            acc.z += tA * wA.z + tB * wB.z;
            acc.w += tA * wA.w + tB * wB.w;
        }
        *(float4*)(xout + (size_t)node * HID + 4 * lane) = acc;

        if (posout != nullptr && lane == 0) {
            float dg = fmaxf(deg[node], 1.0f);
            posout[node * 3 + 0] = posin[node * 3 + 0] + cusum[node * 3 + 0] / dg;
            posout[node * 3 + 1] = posin[node * 3 + 1] + cusum[node * 3 + 1] / dg;
            posout[node * 3 + 2] = posin[node * 3 + 2] + cusum[node * 3 + 2] / dg;
        }
    }
}

// ---------------- pooling ----------------------------------------------------
__global__ void pool_kernel(const float* __restrict__ x,
                            const int* __restrict__ batch,
                            float* __restrict__ gsum, float* __restrict__ gcnt) {
    int node = blockIdx.x * blockDim.x + threadIdx.x;
    int col = blockIdx.y;
    if (node >= N_NODES) return;
    int b = batch[node];
    float v = x[(size_t)node * HID + col];
    unsigned m = __activemask();
    bool full = (m == 0xffffffffu);
    int b0 = __shfl_sync(m, b, 0);
    bool uni = __all_sync(m, b == b0);
    if (full && uni) {
#pragma unroll
        for (int off = 16; off; off >>= 1) v += __shfl_xor_sync(0xffffffffu, v, off);
        if ((threadIdx.x & 31) == 0) {
            atomicAdd(&gsum[b0 * HID + col], v);
            if (col == 0) atomicAdd(&gcnt[b0], 32.0f);
        }
    } else {
        atomicAdd(&gsum[b * HID + col], v);
        if (col == 0) atomicAdd(&gcnt[b], 1.0f);
    }
}

// ---------------- final MLP --------------------------------------------------
__global__ void final_kernel(const float* __restrict__ gsum,
                             const float* __restrict__ gcnt,
                             const float* __restrict__ w1,
                             const float* __restrict__ b1,
                             const float* __restrict__ w2,
                             const float* __restrict__ b2,
                             float* __restrict__ out) {
    int g = blockIdx.x;
    int t = threadIdx.x;  // 128 threads
    __shared__ float sg[HID];
    __shared__ float st[HID];
    float cnt = fmaxf(gcnt[g], 1.0f);
    sg[t] = fmaxf(gsum[g * HID + t] / cnt, 0.0f);   // mean + relu
    __syncthreads();
    float acc = b1[t];
#pragma unroll 8
    for (int j = 0; j < HID; j++) acc += sg[j] * w1[j * HID + t];
    st[t] = fmaxf(acc, 0.0f);
    __syncthreads();
    if (t < OUT_DIM) {
        float o = b2[t];
#pragma unroll 8
        for (int k = 0; k < HID; k++) o += st[k] * w2[k * OUT_DIM + t];
        out[g * OUT_DIM + t] = o;
    }
}

// ---------------- launch -----------------------------------------------------
extern "C" void kernel_launch(void* const* d_in, const int* in_sizes, int n_in,
                              void* d_out, int out_size) {
    const float* x         = (const float*)d_in[0];
    const float* pos       = (const float*)d_in[1];
    const float* edge_attr = (const float*)d_in[2];
    const int* eidx        = (const int*)d_in[3];   // JAX x64 disabled -> int32
    const int* batch       = (const int*)d_in[4];

    const float* mlp_w[2]  = {(const float*)d_in[5],  (const float*)d_in[14]};
    const float* edge_w[2] = {(const float*)d_in[6],  (const float*)d_in[15]};
    const float* edge_b[2] = {(const float*)d_in[7],  (const float*)d_in[16]};
    const float* coord_w[2]= {(const float*)d_in[8],  (const float*)d_in[17]};
    const float* coord_b[2]= {(const float*)d_in[9],  (const float*)d_in[18]};
    const float* nw1[2]    = {(const float*)d_in[10], (const float*)d_in[19]};
    const float* nb1[2]    = {(const float*)d_in[11], (const float*)d_in[20]};
    const float* nw2[2]    = {(const float*)d_in[12], (const float*)d_in[21]};
    const float* nb2[2]    = {(const float*)d_in[13], (const float*)d_in[22]};
    const float* ow1 = (const float*)d_in[23];
    const float* ob1 = (const float*)d_in[24];
    const float* ow2 = (const float*)d_in[25];
    const float* ob2 = (const float*)d_in[26];
    float* out = (float*)d_out;

    float *pa, *pb, *pe, *pc, *pd, *px1, *px2, *ppos, *pgs, *pgc;
    cudaGetSymbolAddress((void**)&pa, g_a);
    cudaGetSymbolAddress((void**)&pb, g_b);
    cudaGetSymbolAddress((void**)&pe, g_eagg);
    cudaGetSymbolAddress((void**)&pc, g_cusum);
    cudaGetSymbolAddress((void**)&pd, g_deg);
    cudaGetSymbolAddress((void**)&px1, g_x1);
    cudaGetSymbolAddress((void**)&px2, g_x2);
    cudaGetSymbolAddress((void**)&ppos, g_pos1);
    cudaGetSymbolAddress((void**)&pgs, g_gsum);
    cudaGetSymbolAddress((void**)&pgc, g_gcnt);

    const int PRE_SMEM  = 2 * F_IN * H_DIM * (int)sizeof(float);                 // 64KB
    const int NODE_SMEM = ((F_IN + H_DIM) * H_DIM + H_DIM * HID + H_DIM + HID) * (int)sizeof(float); // ~81KB
    cudaFuncSetAttribute(precompute_ab, cudaFuncAttributeMaxDynamicSharedMemorySize, PRE_SMEM);
    cudaFuncSetAttribute(node_kernel, cudaFuncAttributeMaxDynamicSharedMemorySize, NODE_SMEM);

    for (int l = 0; l < 2; l++) {
        const float* xin   = l ? px1 : x;
        const float* posin = l ? ppos : pos;
        zero_edge_acc<<<256, 256>>>(pe, pc, pd);
        precompute_ab<<<444, 256, PRE_SMEM>>>(xin, mlp_w[l], pa, pb);
        edge_kernel<<<1184, 256>>>(posin, eidx, edge_attr, mlp_w[l],
                                   edge_w[l], edge_b[l], coord_w[l], coord_b[l],
                                   pa, pb, pe, pc, pd);
        node_kernel<<<296, 256, NODE_SMEM>>>(xin, posin, pe, pc, pd,
                                             nw1[l], nb1[l], nw2[l], nb2[l],
                                             l ? px2 : px1, l ? nullptr : ppos);
    }

    zero_pool<<<32, 256>>>(pgs, pgc);
    dim3 pg((N_NODES + 255) / 256, HID);
    pool_kernel<<<pg, 256>>>(px2, batch, pgs, pgc);
    final_kernel<<<G_GRAPHS, HID>>>(pgs, pgc, ow1, ob1, ow2, ob2, out);
}

// round 3
// speedup vs baseline: 1.3633x; 1.3633x over previous
#include <cuda_runtime.h>

typedef unsigned long long ull;

#define N_NODES 25000
#define N_EDGES 400000
#define F_IN    128
#define D_ATTR  16
#define H_DIM   64
#define HID     128
#define OUT_DIM 32
#define G_GRAPHS 64
#define EPG     4

// ---------------- scratch (device globals) -----------------------------------
__device__ float g_a[N_NODES * H_DIM];
__device__ float g_b[N_NODES * H_DIM];
__device__ float g_eagg[N_NODES * H_DIM];
__device__ float g_t[N_NODES * H_DIM];
__device__ float g_cusum[N_NODES * 3];
__device__ float g_deg[N_NODES];
__device__ float g_x1[N_NODES * HID];
__device__ float g_x2[N_NODES * HID];
__device__ float g_pos1[N_NODES * 3];
__device__ float g_gsum[G_GRAPHS * HID];
__device__ float g_gcnt[G_GRAPHS];

// ---------------- packed f32x2 helpers (sm_103a FFMA2) -----------------------
__device__ __forceinline__ ull fma2(ull a, ull b, ull c) {
    ull d;
    asm("fma.rn.f32x2 %0, %1, %2, %3;" : "=l"(d) : "l"(a), "l"(b), "l"(c));
    return d;
}
__device__ __forceinline__ ull pack2(float x, float y) {
    ull r; asm("mov.b64 %0, {%1, %2};" : "=l"(r) : "f"(x), "f"(y)); return r;
}
__device__ __forceinline__ ull dup2(float x) {
    ull r; asm("mov.b64 %0, {%1, %1};" : "=l"(r) : "f"(x)); return r;
}
__device__ __forceinline__ float2 unpack2(ull v) {
    float lo, hi; asm("mov.b64 {%0, %1}, %2;" : "=f"(lo), "=f"(hi) : "l"(v));
    return make_float2(lo, hi);
}
__device__ __forceinline__ float silu_f(float v) { return v / (1.0f + __expf(-v)); }

// ---------------- precompute: a = x@W_dst, b = x@W_src ------------------------
// mlp_w (273,64): rows [0,128)=W_dst, [128,256)=W_src, [256,272)=W_attr, 272=w_rad
__global__ void __launch_bounds__(256) precompute_ab(const float* __restrict__ x,
                                                     const float* __restrict__ mlp_w,
                                                     float* __restrict__ a,
                                                     float* __restrict__ b) {
    extern __shared__ float sw[];                 // 64KB
    float* s_wd = sw;
    float* s_ws = sw + F_IN * H_DIM;
    for (int i = threadIdx.x; i < F_IN * H_DIM; i += 256) {
        s_wd[i] = mlp_w[i];
        s_ws[i] = mlp_w[F_IN * H_DIM + i];
    }
    __syncthreads();

    int lane = threadIdx.x & 31, k0 = lane * 2;
    int warp = (blockIdx.x * 256 + threadIdx.x) >> 5;
    int nw = gridDim.x * 8;

    for (int node = warp; node < N_NODES; node += nw) {
        const float4* xr = (const float4*)(x + (size_t)node * F_IN);
        ull accA = 0ULL, accB = 0ULL;
#pragma unroll 8
        for (int q = 0; q < 32; q++) {
            float4 xv = xr[q];
            int j = 4 * q;
            ull d;
            d = dup2(xv.x); accA = fma2(d, *(const ull*)(s_wd + (j+0)*H_DIM + k0), accA); accB = fma2(d, *(const ull*)(s_ws + (j+0)*H_DIM + k0), accB);
            d = dup2(xv.y); accA = fma2(d, *(const ull*)(s_wd + (j+1)*H_DIM + k0), accA); accB = fma2(d, *(const ull*)(s_ws + (j+1)*H_DIM + k0), accB);
            d = dup2(xv.z); accA = fma2(d, *(const ull*)(s_wd + (j+2)*H_DIM + k0), accA); accB = fma2(d, *(const ull*)(s_ws + (j+2)*H_DIM + k0), accB);
            d = dup2(xv.w); accA = fma2(d, *(const ull*)(s_wd + (j+3)*H_DIM + k0), accA); accB = fma2(d, *(const ull*)(s_ws + (j+3)*H_DIM + k0), accB);
        }
        *(float2*)(a + (size_t)node * H_DIM + k0) = unpack2(accA);
        *(float2*)(b + (size_t)node * H_DIM + k0) = unpack2(accB);
    }
}

// ---------------- edge kernel: 4 edges/warp, h staged dup'd in smem -----------
__global__ void __launch_bounds__(256) edge_kernel(const float* __restrict__ pos,
                                                   const int* __restrict__ eidx,
                                                   const float* __restrict__ edge_attr,
                                                   const float* __restrict__ mlp_w,
                                                   const float* __restrict__ edge_w,
                                                   const float* __restrict__ edge_b,
                                                   const float* __restrict__ coord_w,
                                                   const float* __restrict__ coord_b,
                                                   const float* __restrict__ a,
                                                   const float* __restrict__ b,
                                                   float* __restrict__ eagg,
                                                   float* __restrict__ cusum,
                                                   float* __restrict__ deg,
                                                   int do_coord) {
    __shared__ float s_ew[H_DIM * H_DIM];        // 16KB
    __shared__ float s_wattr[D_ATTR * H_DIM];    // 4KB
    __shared__ float s_hd[8][EPG * 2 * H_DIM];   // 16KB: (h,h) duplicated per k

    for (int i = threadIdx.x; i < H_DIM * H_DIM; i += 256) s_ew[i] = edge_w[i];
    for (int i = threadIdx.x; i < D_ATTR * H_DIM; i += 256) s_wattr[i] = mlp_w[2 * F_IN * H_DIM + i];
    __syncthreads();

    int lane = threadIdx.x & 31, k0 = lane * 2;
    int wl = threadIdx.x >> 5;
    int warp = (blockIdx.x * 256 + threadIdx.x) >> 5;
    int nw = gridDim.x * 8;
    float* s_h = s_hd[wl];

    // hoisted per-lane constants
    ull wrp = pack2(mlp_w[(2 * F_IN + D_ATTR) * H_DIM + k0],
                    mlp_w[(2 * F_IN + D_ATTR) * H_DIM + k0 + 1]);
    ull ebp = pack2(edge_b[k0], edge_b[k0 + 1]);
    float cw0 = coord_w[k0], cw1 = coord_w[k0 + 1];
    float cb = coord_b[0];

    const int NGROUPS = N_EDGES / EPG;           // 100000 exactly
    for (int g = warp; g < NGROUPS; g += nw) {
        int ebase = g * EPG;
        int dstv[EPG];
        float dxv[EPG], dyv[EPG], dzv[EPG];

        // ---- phase 1: per-edge h (lane holds h[k0],h[k0+1]) -> smem dup'd
#pragma unroll
        for (int t = 0; t < EPG; t++) {
            int e = ebase + t;
            int src = eidx[e];
            int dst = eidx[N_EDGES + e];
            dstv[t] = dst;
            float dx = pos[dst * 3 + 0] - pos[src * 3 + 0];
            float dy = pos[dst * 3 + 1] - pos[src * 3 + 1];
            float dz = pos[dst * 3 + 2] - pos[src * 3 + 2];
            dxv[t] = dx; dyv[t] = dy; dzv[t] = dz;
            float radial = dx * dx + dy * dy + dz * dz;

            float2 av = *(const float2*)(a + (size_t)dst * H_DIM + k0);
            float2 bv = *(const float2*)(b + (size_t)src * H_DIM + k0);
            ull h = fma2(dup2(radial), wrp, pack2(av.x + bv.x, av.y + bv.y));

            const float4* eat = (const float4*)(edge_attr + (size_t)e * D_ATTR);
#pragma unroll
            for (int q = 0; q < 4; q++) {
                float4 ev = eat[q];
                int d = 4 * q;
                h = fma2(dup2(ev.x), *(const ull*)(s_wattr + (d+0)*H_DIM + k0), h);
                h = fma2(dup2(ev.y), *(const ull*)(s_wattr + (d+1)*H_DIM + k0), h);
                h = fma2(dup2(ev.z), *(const ull*)(s_wattr + (d+2)*H_DIM + k0), h);
                h = fma2(dup2(ev.w), *(const ull*)(s_wattr + (d+3)*H_DIM + k0), h);
            }
            float2 hf = unpack2(h);
            float h0 = silu_f(hf.x), h1 = silu_f(hf.y);
            *(float4*)(s_h + t * 2 * H_DIM + 4 * lane) = make_float4(h0, h0, h1, h1);
        }
        __syncwarp();

        // ---- phase 2: e = silu(h @ edge_w + eb), packed col-pair per lane
        ull acc[EPG];
#pragma unroll
        for (int t = 0; t < EPG; t++) acc[t] = ebp;
#pragma unroll
        for (int kc = 0; kc < 32; kc++) {
            ull w0 = *(const ull*)(s_ew + (2 * kc) * H_DIM + k0);
            ull w1 = *(const ull*)(s_ew + (2 * kc + 1) * H_DIM + k0);
#pragma unroll
            for (int t = 0; t < EPG; t++) {
                ulonglong2 hv = *(const ulonglong2*)(s_h + t * 2 * H_DIM + 4 * kc);
                acc[t] = fma2(w0, hv.x, acc[t]);
                acc[t] = fma2(w1, hv.y, acc[t]);
            }
        }
        __syncwarp();

        // ---- epilogue
        float part[EPG];
#pragma unroll
        for (int t = 0; t < EPG; t++) {
            float2 v = unpack2(acc[t]);
            float e0 = silu_f(v.x), e1 = silu_f(v.y);
            atomicAdd(eagg + (size_t)dstv[t] * H_DIM + k0, e0);
            atomicAdd(eagg + (size_t)dstv[t] * H_DIM + k0 + 1, e1);
            part[t] = e0 * cw0 + e1 * cw1;
        }
        if (do_coord) {
            float ss[EPG];
#pragma unroll
            for (int t = 0; t < EPG; t++) {
                float p = part[t];
                p += __shfl_xor_sync(0xffffffffu, p, 16);
                p += __shfl_xor_sync(0xffffffffu, p, 8);
                p += __shfl_xor_sync(0xffffffffu, p, 4);
                p += __shfl_xor_sync(0xffffffffu, p, 2);
                p += __shfl_xor_sync(0xffffffffu, p, 1);
                ss[t] = silu_f(p + cb);
            }
#pragma unroll
            for (int t = 0; t < EPG; t++) {
                if (lane == t) {
                    int d3 = dstv[t] * 3;
                    atomicAdd(cusum + d3 + 0, dxv[t] * ss[t]);
                    atomicAdd(cusum + d3 + 1, dyv[t] * ss[t]);
                    atomicAdd(cusum + d3 + 2, dzv[t] * ss[t]);
                    atomicAdd(deg + dstv[t], 1.0f);
                }
            }
        }
    }
}

// ---------------- node stage 1: t = silu([x,eagg]@w1 + b1) --------------------
__global__ void __launch_bounds__(256) node1_kernel(const float* __restrict__ xin,
                                                    const float* __restrict__ eagg,
                                                    const float* __restrict__ nw1,
                                                    const float* __restrict__ nb1,
                                                    float* __restrict__ tout) {
    extern __shared__ float s_w1[];              // 48KB
    for (int i = threadIdx.x; i < (F_IN + H_DIM) * H_DIM; i += 256) s_w1[i] = nw1[i];
    __syncthreads();

    int lane = threadIdx.x & 31, k0 = lane * 2;
    int warp = (blockIdx.x * 256 + threadIdx.x) >> 5;
    int nw = gridDim.x * 8;
    ull bp = pack2(nb1[k0], nb1[k0 + 1]);

    for (int node = warp; node < N_NODES; node += nw) {
        ull acc = bp;
        const float4* xr = (const float4*)(xin + (size_t)node * F_IN);
#pragma unroll 8
        for (int q = 0; q < 32; q++) {
            float4 xv = xr[q];
            int j = 4 * q;
            acc = fma2(dup2(xv.x), *(const ull*)(s_w1 + (j+0)*H_DIM + k0), acc);
            acc = fma2(dup2(xv.y), *(const ull*)(s_w1 + (j+1)*H_DIM + k0), acc);
            acc = fma2(dup2(xv.z), *(const ull*)(s_w1 + (j+2)*H_DIM + k0), acc);
            acc = fma2(dup2(xv.w), *(const ull*)(s_w1 + (j+3)*H_DIM + k0), acc);
        }
        const float4* er = (const float4*)(eagg + (size_t)node * H_DIM);
#pragma unroll 8
        for (int q = 0; q < 16; q++) {
            float4 ev = er[q];
            int j = F_IN + 4 * q;
            acc = fma2(dup2(ev.x), *(const ull*)(s_w1 + (j+0)*H_DIM + k0), acc);
            acc = fma2(dup2(ev.y), *(const ull*)(s_w1 + (j+1)*H_DIM + k0), acc);
            acc = fma2(dup2(ev.z), *(const ull*)(s_w1 + (j+2)*H_DIM + k0), acc);
            acc = fma2(dup2(ev.w), *(const ull*)(s_w1 + (j+3)*H_DIM + k0), acc);
        }
        float2 tv = unpack2(acc);
        *(float2*)(tout + (size_t)node * H_DIM + k0) = make_float2(silu_f(tv.x), silu_f(tv.y));
    }
}

// ---------------- node stage 2: xout = t@w2 + b2 (+pos update) ----------------
__global__ void __launch_bounds__(256) node2_kernel(const float* __restrict__ tin,
                                                    const float* __restrict__ nw2,
                                                    const float* __restrict__ nb2,
                                                    const float* __restrict__ posin,
                                                    const float* __restrict__ cusum,
                                                    const float* __restrict__ deg,
                                                    float* __restrict__ xout,
                                                    float* __restrict__ posout) {
    __shared__ float s_w2[H_DIM * HID];          // 32KB
    for (int i = threadIdx.x; i < H_DIM * HID; i += 256) s_w2[i] = nw2[i];
    __syncthreads();

    int lane = threadIdx.x & 31, k0 = lane * 2;
    int warp = (blockIdx.x * 256 + threadIdx.x) >> 5;
    int nw = gridDim.x * 8;
    ull b0p = pack2(nb2[k0], nb2[k0 + 1]);
    ull b1p = pack2(nb2[H_DIM + k0], nb2[H_DIM + k0 + 1]);

    for (int node = warp; node < N_NODES; node += nw) {
        ull a0 = b0p, a1 = b1p;
        const float4* tr = (const float4*)(tin + (size_t)node * H_DIM);
#pragma unroll 4
        for (int q = 0; q < 16; q++) {
            float4 tv = tr[q];
            int j = 4 * q;
            ull d;
            d = dup2(tv.x); a0 = fma2(d, *(const ull*)(s_w2 + (j+0)*HID + k0), a0); a1 = fma2(d, *(const ull*)(s_w2 + (j+0)*HID + H_DIM + k0), a1);
            d = dup2(tv.y); a0 = fma2(d, *(const ull*)(s_w2 + (j+1)*HID + k0), a0); a1 = fma2(d, *(const ull*)(s_w2 + (j+1)*HID + H_DIM + k0), a1);
            d = dup2(tv.z); a0 = fma2(d, *(const ull*)(s_w2 + (j+2)*HID + k0), a0); a1 = fma2(d, *(const ull*)(s_w2 + (j+2)*HID + H_DIM + k0), a1);
            d = dup2(tv.w); a0 = fma2(d, *(const ull*)(s_w2 + (j+3)*HID + k0), a0); a1 = fma2(d, *(const ull*)(s_w2 + (j+3)*HID + H_DIM + k0), a1);
        }
        *(float2*)(xout + (size_t)node * HID + k0) = unpack2(a0);
        *(float2*)(xout + (size_t)node * HID + H_DIM + k0) = unpack2(a1);

        if (posout != nullptr && lane == 0) {
            float dg = fmaxf(deg[node], 1.0f);
            posout[node * 3 + 0] = posin[node * 3 + 0] + cusum[node * 3 + 0] / dg;
            posout[node * 3 + 1] = posin[node * 3 + 1] + cusum[node * 3 + 1] / dg;
            posout[node * 3 + 2] = posin[node * 3 + 2] + cusum[node * 3 + 2] / dg;
        }
    }
}

// ---------------- pooling: warp per 8-node chunk (batch sorted) ---------------
__global__ void pool_kernel(const float* __restrict__ x,
                            const int* __restrict__ batch,
                            float* __restrict__ gsum, float* __restrict__ gcnt) {
    int lane = threadIdx.x & 31;
    int warp = (blockIdx.x * blockDim.x + threadIdx.x) >> 5;
    int nw = (gridDim.x * blockDim.x) >> 5;
    int nchunks = (N_NODES + 7) / 8;

    for (int c = warp; c < nchunks; c += nw) {
        int base = c * 8;
        float4 acc = make_float4(0.f, 0.f, 0.f, 0.f);
        int curb = batch[base];
        float cnt = 0.f;
        for (int i = 0; i < 8; i++) {
            int node = base + i;
            if (node >= N_NODES) break;
            int bb = batch[node];
            if (bb != curb) {
                float* gs = gsum + curb * HID + 4 * lane;
                atomicAdd(gs + 0, acc.x); atomicAdd(gs + 1, acc.y);
                atomicAdd(gs + 2, acc.z); atomicAdd(gs + 3, acc.w);
                if (lane == 0) atomicAdd(&gcnt[curb], cnt);
                acc = make_float4(0.f, 0.f, 0.f, 0.f);
                cnt = 0.f;
                curb = bb;
            }
            float4 v = *(const float4*)(x + (size_t)node * HID + 4 * lane);
            acc.x += v.x; acc.y += v.y; acc.z += v.z; acc.w += v.w;
            cnt += 1.f;
        }
        float* gs = gsum + curb * HID + 4 * lane;
        atomicAdd(gs + 0, acc.x); atomicAdd(gs + 1, acc.y);
        atomicAdd(gs + 2, acc.z); atomicAdd(gs + 3, acc.w);
        if (lane == 0) atomicAdd(&gcnt[curb], cnt);
    }
}

// ---------------- final MLP ---------------------------------------------------
__global__ void final_kernel(const float* __restrict__ gsum,
                             const float* __restrict__ gcnt,
                             const float* __restrict__ w1,
                             const float* __restrict__ b1,
                             const float* __restrict__ w2,
                             const float* __restrict__ b2,
                             float* __restrict__ out) {
    int g = blockIdx.x;
    int t = threadIdx.x;  // 128 threads
    __shared__ float sg[HID];
    __shared__ float st[HID];
    float cnt = fmaxf(gcnt[g], 1.0f);
    sg[t] = fmaxf(gsum[g * HID + t] / cnt, 0.0f);
    __syncthreads();
    float acc = b1[t];
#pragma unroll 8
    for (int j = 0; j < HID; j++) acc += sg[j] * w1[j * HID + t];
    st[t] = fmaxf(acc, 0.0f);
    __syncthreads();
    if (t < OUT_DIM) {
        float o = b2[t];
#pragma unroll 8
        for (int k = 0; k < HID; k++) o += st[k] * w2[k * OUT_DIM + t];
        out[g * OUT_DIM + t] = o;
    }
}

// ---------------- launch ------------------------------------------------------
extern "C" void kernel_launch(void* const* d_in, const int* in_sizes, int n_in,
                              void* d_out, int out_size) {
    const float* x         = (const float*)d_in[0];
    const float* pos       = (const float*)d_in[1];
    const float* edge_attr = (const float*)d_in[2];
    const int* eidx        = (const int*)d_in[3];
    const int* batch       = (const int*)d_in[4];

    const float* mlp_w[2]  = {(const float*)d_in[5],  (const float*)d_in[14]};
    const float* edge_w[2] = {(const float*)d_in[6],  (const float*)d_in[15]};
    const float* edge_b[2] = {(const float*)d_in[7],  (const float*)d_in[16]};
    const float* coord_w[2]= {(const float*)d_in[8],  (const float*)d_in[17]};
    const float* coord_b[2]= {(const float*)d_in[9],  (const float*)d_in[18]};
    const float* nw1[2]    = {(const float*)d_in[10], (const float*)d_in[19]};
    const float* nb1[2]    = {(const float*)d_in[11], (const float*)d_in[20]};
    const float* nw2[2]    = {(const float*)d_in[12], (const float*)d_in[21]};
    const float* nb2[2]    = {(const float*)d_in[13], (const float*)d_in[22]};
    const float* ow1 = (const float*)d_in[23];
    const float* ob1 = (const float*)d_in[24];
    const float* ow2 = (const float*)d_in[25];
    const float* ob2 = (const float*)d_in[26];
    float* out = (float*)d_out;

    float *pa, *pb, *pe, *pt, *pc, *pd, *px1, *px2, *ppos, *pgs, *pgc;
    cudaGetSymbolAddress((void**)&pa, g_a);
    cudaGetSymbolAddress((void**)&pb, g_b);
    cudaGetSymbolAddress((void**)&pe, g_eagg);
    cudaGetSymbolAddress((void**)&pt, g_t);
    cudaGetSymbolAddress((void**)&pc, g_cusum);
    cudaGetSymbolAddress((void**)&pd, g_deg);
    cudaGetSymbolAddress((void**)&px1, g_x1);
    cudaGetSymbolAddress((void**)&px2, g_x2);
    cudaGetSymbolAddress((void**)&ppos, g_pos1);
    cudaGetSymbolAddress((void**)&pgs, g_gsum);
    cudaGetSymbolAddress((void**)&pgc, g_gcnt);

    const int PRE_SMEM  = 2 * F_IN * H_DIM * (int)sizeof(float);          // 64KB
    const int N1_SMEM   = (F_IN + H_DIM) * H_DIM * (int)sizeof(float);    // 48KB
    cudaFuncSetAttribute(precompute_ab, cudaFuncAttributeMaxDynamicSharedMemorySize, PRE_SMEM);
    cudaFuncSetAttribute(node1_kernel, cudaFuncAttributeMaxDynamicSharedMemorySize, N1_SMEM);

    for (int l = 0; l < 2; l++) {
        const float* xin   = l ? px1 : x;
        const float* posin = l ? ppos : pos;
        cudaMemsetAsync(pe, 0, (size_t)N_NODES * H_DIM * sizeof(float));
        if (l == 0) {
            cudaMemsetAsync(pc, 0, (size_t)N_NODES * 3 * sizeof(float));
            cudaMemsetAsync(pd, 0, (size_t)N_NODES * sizeof(float));
        }
        precompute_ab<<<444, 256, PRE_SMEM>>>(xin, mlp_w[l], pa, pb);
        edge_kernel<<<888, 256>>>(posin, eidx, edge_attr, mlp_w[l],
                                  edge_w[l], edge_b[l], coord_w[l], coord_b[l],
                                  pa, pb, pe, pc, pd, l == 0 ? 1 : 0);
        node1_kernel<<<444, 256, N1_SMEM>>>(xin, pe, nw1[l], nb1[l], pt);
        node2_kernel<<<444, 256>>>(pt, nw2[l], nb2[l], posin, pc, pd,
                                   l ? px2 : px1, l == 0 ? ppos : nullptr);
    }

    cudaMemsetAsync(pgs, 0, (size_t)G_GRAPHS * HID * sizeof(float));
    cudaMemsetAsync(pgc, 0, (size_t)G_GRAPHS * sizeof(float));
    pool_kernel<<<64, 256>>>(px2, batch, pgs, pgc);
    final_kernel<<<G_GRAPHS, HID>>>(pgs, pgc, ow1, ob1, ow2, ob2, out);
}

// round 4
// speedup vs baseline: 1.5730x; 1.1538x over previous
#include <cuda_runtime.h>

typedef unsigned long long ull;

#define N_NODES 25000
#define N_EDGES 400000
#define F_IN    128
#define D_ATTR  16
#define H_DIM   64
#define HID     128
#define OUT_DIM 32
#define G_GRAPHS 64
#define EPG     8
#define NPG     4

// ---------------- scratch (device globals) -----------------------------------
__device__ float g_a[N_NODES * H_DIM];
__device__ float g_b[N_NODES * H_DIM];
__device__ float g_eagg[N_NODES * H_DIM];
__device__ float g_t[N_NODES * H_DIM];
__device__ float g_cusum[N_NODES * 3];
__device__ float g_deg[N_NODES];
__device__ float g_x1[N_NODES * HID];
__device__ float g_pos1[N_NODES * 3];
__device__ float g_gsum[G_GRAPHS * H_DIM];
__device__ float g_gcnt[G_GRAPHS];

// ---------------- packed f32x2 helpers (sm_103a FFMA2) -----------------------
__device__ __forceinline__ ull fma2(ull a, ull b, ull c) {
    ull d;
    asm("fma.rn.f32x2 %0, %1, %2, %3;" : "=l"(d) : "l"(a), "l"(b), "l"(c));
    return d;
}
__device__ __forceinline__ ull pack2(float x, float y) {
    ull r; asm("mov.b64 %0, {%1, %2};" : "=l"(r) : "f"(x), "f"(y)); return r;
}
__device__ __forceinline__ ull dup2(float x) {
    ull r; asm("mov.b64 %0, {%1, %1};" : "=l"(r) : "f"(x)); return r;
}
__device__ __forceinline__ float2 unpack2(ull v) {
    float lo, hi; asm("mov.b64 {%0, %1}, %2;" : "=f"(lo), "=f"(hi) : "l"(v));
    return make_float2(lo, hi);
}
__device__ __forceinline__ void red_add_v2(float* a, float x, float y) {
    asm volatile("red.global.add.v2.f32 [%0], {%1, %2};"
                 :: "l"(a), "f"(x), "f"(y) : "memory");
}
__device__ __forceinline__ float silu_f(float v) { return v / (1.0f + __expf(-v)); }

// ---------------- precompute: a = x@W_dst, b = x@W_src (4 nodes/warp) --------
// mlp_w (273,64): rows [0,128)=W_dst, [128,256)=W_src, [256,272)=W_attr, 272=w_rad
__global__ void __launch_bounds__(256) precompute_ab(const float* __restrict__ x,
                                                     const float* __restrict__ mlp_w,
                                                     float* __restrict__ a,
                                                     float* __restrict__ b) {
    extern __shared__ float sw[];                 // 64KB
    float* s_wd = sw;
    float* s_ws = sw + F_IN * H_DIM;
    for (int i = threadIdx.x; i < F_IN * H_DIM; i += 256) {
        s_wd[i] = mlp_w[i];
        s_ws[i] = mlp_w[F_IN * H_DIM + i];
    }
    __syncthreads();

    int lane = threadIdx.x & 31, k0 = lane * 2;
    int warp = (blockIdx.x * 256 + threadIdx.x) >> 5;
    int nw = gridDim.x * 8;
    const int NG = N_NODES / NPG;                 // 6250

    for (int g = warp; g < NG; g += nw) {
        int nbase = g * NPG;
        ull accA[NPG], accB[NPG];
#pragma unroll
        for (int t = 0; t < NPG; t++) { accA[t] = 0ULL; accB[t] = 0ULL; }
#pragma unroll 4
        for (int q = 0; q < 32; q++) {
            float4 xv[NPG];
#pragma unroll
            for (int t = 0; t < NPG; t++)
                xv[t] = *(const float4*)(x + (size_t)(nbase + t) * F_IN + 4 * q);
            ull wd0 = *(const ull*)(s_wd + (4*q+0)*H_DIM + k0);
            ull wd1 = *(const ull*)(s_wd + (4*q+1)*H_DIM + k0);
            ull wd2 = *(const ull*)(s_wd + (4*q+2)*H_DIM + k0);
            ull wd3 = *(const ull*)(s_wd + (4*q+3)*H_DIM + k0);
            ull ws0 = *(const ull*)(s_ws + (4*q+0)*H_DIM + k0);
            ull ws1 = *(const ull*)(s_ws + (4*q+1)*H_DIM + k0);
            ull ws2 = *(const ull*)(s_ws + (4*q+2)*H_DIM + k0);
            ull ws3 = *(const ull*)(s_ws + (4*q+3)*H_DIM + k0);
#pragma unroll
            for (int t = 0; t < NPG; t++) {
                ull d;
                d = dup2(xv[t].x); accA[t] = fma2(d, wd0, accA[t]); accB[t] = fma2(d, ws0, accB[t]);
                d = dup2(xv[t].y); accA[t] = fma2(d, wd1, accA[t]); accB[t] = fma2(d, ws1, accB[t]);
                d = dup2(xv[t].z); accA[t] = fma2(d, wd2, accA[t]); accB[t] = fma2(d, ws2, accB[t]);
                d = dup2(xv[t].w); accA[t] = fma2(d, wd3, accA[t]); accB[t] = fma2(d, ws3, accB[t]);
            }
        }
#pragma unroll
        for (int t = 0; t < NPG; t++) {
            *(float2*)(a + (size_t)(nbase + t) * H_DIM + k0) = unpack2(accA[t]);
            *(float2*)(b + (size_t)(nbase + t) * H_DIM + k0) = unpack2(accB[t]);
        }
    }
}

// ---------------- edge kernel: 8 edges/warp -----------------------------------
__global__ void __launch_bounds__(256) edge_kernel(const float* __restrict__ pos,
                                                   const int* __restrict__ eidx,
                                                   const float* __restrict__ edge_attr,
                                                   const float* __restrict__ mlp_w,
                                                   const float* __restrict__ edge_w,
                                                   const float* __restrict__ edge_b,
                                                   const float* __restrict__ coord_w,
                                                   const float* __restrict__ coord_b,
                                                   const float* __restrict__ a,
                                                   const float* __restrict__ b,
                                                   float* __restrict__ eagg,
                                                   float* __restrict__ cusum,
                                                   float* __restrict__ deg,
                                                   int do_coord) {
    extern __shared__ float sm[];
    float* s_ew    = sm;                                 // 4096 floats
    float* s_wattr = sm + H_DIM * H_DIM;                 // 1024 floats
    float* s_hall  = s_wattr + D_ATTR * H_DIM;           // 8 warps * 1024 floats

    for (int i = threadIdx.x; i < H_DIM * H_DIM; i += 256) s_ew[i] = edge_w[i];
    for (int i = threadIdx.x; i < D_ATTR * H_DIM; i += 256)
        s_wattr[i] = mlp_w[2 * F_IN * H_DIM + i];
    __syncthreads();

    int lane = threadIdx.x & 31, k0 = lane * 2;
    int wl = threadIdx.x >> 5;
    int warp = (blockIdx.x * 256 + threadIdx.x) >> 5;
    int nw = gridDim.x * 8;
    float* s_h = s_hall + wl * (EPG * 2 * H_DIM);

    ull wrp = pack2(mlp_w[(2 * F_IN + D_ATTR) * H_DIM + k0],
                    mlp_w[(2 * F_IN + D_ATTR) * H_DIM + k0 + 1]);
    ull ebp = pack2(edge_b[k0], edge_b[k0 + 1]);
    float cw0 = coord_w[k0], cw1 = coord_w[k0 + 1];
    float cb = coord_b[0];

    const int NGROUPS = N_EDGES / EPG;            // 50000
    for (int g = warp; g < NGROUPS; g += nw) {
        int ebase = g * EPG;
        int dstv[EPG];
        float mydx = 0.f, mydy = 0.f, mydz = 0.f;  // lane t keeps edge t's diff
        ull h[EPG];

        // ---- phase 1a: pos/radial + a[dst]+b[src]
#pragma unroll
        for (int t = 0; t < EPG; t++) {
            int e = ebase + t;
            int src = eidx[e];
            int dst = eidx[N_EDGES + e];
            dstv[t] = dst;
            float dx = pos[dst * 3 + 0] - pos[src * 3 + 0];
            float dy = pos[dst * 3 + 1] - pos[src * 3 + 1];
            float dz = pos[dst * 3 + 2] - pos[src * 3 + 2];
            if (lane == t) { mydx = dx; mydy = dy; mydz = dz; }
            float radial = dx * dx + dy * dy + dz * dz;
            float2 av = *(const float2*)(a + (size_t)dst * H_DIM + k0);
            float2 bv = *(const float2*)(b + (size_t)src * H_DIM + k0);
            h[t] = fma2(dup2(radial), wrp, pack2(av.x + bv.x, av.y + bv.y));
        }

        // ---- phase 1b: + edge_attr @ W_attr (weights amortized over 8 edges)
#pragma unroll
        for (int q = 0; q < 4; q++) {
            float4 ev[EPG];
#pragma unroll
            for (int t = 0; t < EPG; t++)
                ev[t] = *(const float4*)(edge_attr + (size_t)(ebase + t) * D_ATTR + 4 * q);
            ull w0 = *(const ull*)(s_wattr + (4*q+0)*H_DIM + k0);
            ull w1 = *(const ull*)(s_wattr + (4*q+1)*H_DIM + k0);
            ull w2 = *(const ull*)(s_wattr + (4*q+2)*H_DIM + k0);
            ull w3 = *(const ull*)(s_wattr + (4*q+3)*H_DIM + k0);
#pragma unroll
            for (int t = 0; t < EPG; t++) {
                h[t] = fma2(dup2(ev[t].x), w0, h[t]);
                h[t] = fma2(dup2(ev[t].y), w1, h[t]);
                h[t] = fma2(dup2(ev[t].z), w2, h[t]);
                h[t] = fma2(dup2(ev[t].w), w3, h[t]);
            }
        }

        // ---- silu + stage (h,h) duplicated in smem
#pragma unroll
        for (int t = 0; t < EPG; t++) {
            float2 hf = unpack2(h[t]);
            float h0 = silu_f(hf.x), h1 = silu_f(hf.y);
            *(float4*)(s_h + t * 2 * H_DIM + 4 * lane) = make_float4(h0, h0, h1, h1);
        }
        __syncwarp();

        // ---- phase 2: e = silu(h @ edge_w + eb)
        ull acc[EPG];
#pragma unroll
        for (int t = 0; t < EPG; t++) acc[t] = ebp;
#pragma unroll 8
        for (int kc = 0; kc < 32; kc++) {
            ull w0 = *(const ull*)(s_ew + (2 * kc) * H_DIM + k0);
            ull w1 = *(const ull*)(s_ew + (2 * kc + 1) * H_DIM + k0);
#pragma unroll
            for (int t = 0; t < EPG; t++) {
                ulonglong2 hv = *(const ulonglong2*)(s_h + t * 2 * H_DIM + 4 * kc);
                acc[t] = fma2(w0, hv.x, acc[t]);
                acc[t] = fma2(w1, hv.y, acc[t]);
            }
        }
        __syncwarp();

        // ---- epilogue: scatter + coord
        float myss = 0.f;
#pragma unroll
        for (int t = 0; t < EPG; t++) {
            float2 v = unpack2(acc[t]);
            float e0 = silu_f(v.x), e1 = silu_f(v.y);
            red_add_v2(eagg + (size_t)dstv[t] * H_DIM + k0, e0, e1);
            if (do_coord) {
                float p = e0 * cw0 + e1 * cw1;
                p += __shfl_xor_sync(0xffffffffu, p, 16);
                p += __shfl_xor_sync(0xffffffffu, p, 8);
                p += __shfl_xor_sync(0xffffffffu, p, 4);
                p += __shfl_xor_sync(0xffffffffu, p, 2);
                p += __shfl_xor_sync(0xffffffffu, p, 1);
                if (lane == t) myss = silu_f(p + cb);
            }
        }
        if (do_coord && lane < EPG) {
            int d3 = dstv[lane] * 3;
            atomicAdd(cusum + d3 + 0, mydx * myss);
            atomicAdd(cusum + d3 + 1, mydy * myss);
            atomicAdd(cusum + d3 + 2, mydz * myss);
            atomicAdd(deg + dstv[lane], 1.0f);
        }
    }
}

// ---------------- node stage 1: t = silu([x,eagg]@w1 + b1), 4 nodes/warp ------
__global__ void __launch_bounds__(256) node1_kernel(const float* __restrict__ xin,
                                                    const float* __restrict__ eagg,
                                                    const float* __restrict__ nw1,
                                                    const float* __restrict__ nb1,
                                                    float* __restrict__ tout) {
    extern __shared__ float s_w1[];               // 48KB
    for (int i = threadIdx.x; i < (F_IN + H_DIM) * H_DIM; i += 256) s_w1[i] = nw1[i];
    __syncthreads();

    int lane = threadIdx.x & 31, k0 = lane * 2;
    int warp = (blockIdx.x * 256 + threadIdx.x) >> 5;
    int nw = gridDim.x * 8;
    ull bp = pack2(nb1[k0], nb1[k0 + 1]);
    const int NG = N_NODES / NPG;

    for (int g = warp; g < NG; g += nw) {
        int nbase = g * NPG;
        ull acc[NPG];
#pragma unroll
        for (int t = 0; t < NPG; t++) acc[t] = bp;
#pragma unroll 4
        for (int q = 0; q < 32; q++) {
            float4 xv[NPG];
#pragma unroll
            for (int t = 0; t < NPG; t++)
                xv[t] = *(const float4*)(xin + (size_t)(nbase + t) * F_IN + 4 * q);
            ull w0 = *(const ull*)(s_w1 + (4*q+0)*H_DIM + k0);
            ull w1 = *(const ull*)(s_w1 + (4*q+1)*H_DIM + k0);
            ull w2 = *(const ull*)(s_w1 + (4*q+2)*H_DIM + k0);
            ull w3 = *(const ull*)(s_w1 + (4*q+3)*H_DIM + k0);
#pragma unroll
            for (int t = 0; t < NPG; t++) {
                acc[t] = fma2(dup2(xv[t].x), w0, acc[t]);
                acc[t] = fma2(dup2(xv[t].y), w1, acc[t]);
                acc[t] = fma2(dup2(xv[t].z), w2, acc[t]);
                acc[t] = fma2(dup2(xv[t].w), w3, acc[t]);
            }
        }
#pragma unroll 4
        for (int q = 0; q < 16; q++) {
            float4 ev[NPG];
#pragma unroll
            for (int t = 0; t < NPG; t++)
                ev[t] = *(const float4*)(eagg + (size_t)(nbase + t) * H_DIM + 4 * q);
            int j = F_IN + 4 * q;
            ull w0 = *(const ull*)(s_w1 + (j+0)*H_DIM + k0);
            ull w1 = *(const ull*)(s_w1 + (j+1)*H_DIM + k0);
            ull w2 = *(const ull*)(s_w1 + (j+2)*H_DIM + k0);
            ull w3 = *(const ull*)(s_w1 + (j+3)*H_DIM + k0);
#pragma unroll
            for (int t = 0; t < NPG; t++) {
                acc[t] = fma2(dup2(ev[t].x), w0, acc[t]);
                acc[t] = fma2(dup2(ev[t].y), w1, acc[t]);
                acc[t] = fma2(dup2(ev[t].z), w2, acc[t]);
                acc[t] = fma2(dup2(ev[t].w), w3, acc[t]);
            }
        }
#pragma unroll
        for (int t = 0; t < NPG; t++) {
            float2 tv = unpack2(acc[t]);
            *(float2*)(tout + (size_t)(nbase + t) * H_DIM + k0) =
                make_float2(silu_f(tv.x), silu_f(tv.y));
        }
    }
}

// ---------------- node stage 2 (layer 0 only): x1 = t@w2 + b2, pos update -----
__global__ void __launch_bounds__(256) node2_kernel(const float* __restrict__ tin,
                                                    const float* __restrict__ nw2,
                                                    const float* __restrict__ nb2,
                                                    const float* __restrict__ posin,
                                                    const float* __restrict__ cusum,
                                                    const float* __restrict__ deg,
                                                    float* __restrict__ xout,
                                                    float* __restrict__ posout) {
    __shared__ float s_w2[H_DIM * HID];           // 32KB
    for (int i = threadIdx.x; i < H_DIM * HID; i += 256) s_w2[i] = nw2[i];
    __syncthreads();

    int lane = threadIdx.x & 31, k0 = lane * 2;
    int warp = (blockIdx.x * 256 + threadIdx.x) >> 5;
    int nw = gridDim.x * 8;
    ull b0p = pack2(nb2[k0], nb2[k0 + 1]);
    ull b1p = pack2(nb2[H_DIM + k0], nb2[H_DIM + k0 + 1]);
    const int NG = N_NODES / NPG;

    for (int g = warp; g < NG; g += nw) {
        int nbase = g * NPG;
        ull a0[NPG], a1[NPG];
#pragma unroll
        for (int t = 0; t < NPG; t++) { a0[t] = b0p; a1[t] = b1p; }
#pragma unroll 4
        for (int q = 0; q < 16; q++) {
            float4 tv[NPG];
#pragma unroll
            for (int t = 0; t < NPG; t++)
                tv[t] = *(const float4*)(tin + (size_t)(nbase + t) * H_DIM + 4 * q);
            ull wl0 = *(const ull*)(s_w2 + (4*q+0)*HID + k0);
            ull wh0 = *(const ull*)(s_w2 + (4*q+0)*HID + H_DIM + k0);
            ull wl1 = *(const ull*)(s_w2 + (4*q+1)*HID + k0);
            ull wh1 = *(const ull*)(s_w2 + (4*q+1)*HID + H_DIM + k0);
            ull wl2 = *(const ull*)(s_w2 + (4*q+2)*HID + k0);
            ull wh2 = *(const ull*)(s_w2 + (4*q+2)*HID + H_DIM + k0);
            ull wl3 = *(const ull*)(s_w2 + (4*q+3)*HID + k0);
            ull wh3 = *(const ull*)(s_w2 + (4*q+3)*HID + H_DIM + k0);
#pragma unroll
            for (int t = 0; t < NPG; t++) {
                ull d;
                d = dup2(tv[t].x); a0[t] = fma2(d, wl0, a0[t]); a1[t] = fma2(d, wh0, a1[t]);
                d = dup2(tv[t].y); a0[t] = fma2(d, wl1, a0[t]); a1[t] = fma2(d, wh1, a1[t]);
                d = dup2(tv[t].z); a0[t] = fma2(d, wl2, a0[t]); a1[t] = fma2(d, wh2, a1[t]);
                d = dup2(tv[t].w); a0[t] = fma2(d, wl3, a0[t]); a1[t] = fma2(d, wh3, a1[t]);
            }
        }
#pragma unroll
        for (int t = 0; t < NPG; t++) {
            *(float2*)(xout + (size_t)(nbase + t) * HID + k0) = unpack2(a0[t]);
            *(float2*)(xout + (size_t)(nbase + t) * HID + H_DIM + k0) = unpack2(a1[t]);
        }
        if (lane < NPG) {
            int node = nbase + lane;
            float dg = fmaxf(deg[node], 1.0f);
            posout[node * 3 + 0] = posin[node * 3 + 0] + cusum[node * 3 + 0] / dg;
            posout[node * 3 + 1] = posin[node * 3 + 1] + cusum[node * 3 + 1] / dg;
            posout[node * 3 + 2] = posin[node * 3 + 2] + cusum[node * 3 + 2] / dg;
        }
    }
}

// ---------------- pooling of t (H=64), batch sorted ----------------------------
__global__ void pool_kernel(const float* __restrict__ t,
                            const int* __restrict__ batch,
                            float* __restrict__ gsum, float* __restrict__ gcnt) {
    int lane = threadIdx.x & 31;
    int warp = (blockIdx.x * blockDim.x + threadIdx.x) >> 5;
    int nw = (gridDim.x * blockDim.x) >> 5;
    int nchunks = (N_NODES + 7) / 8;

    for (int c = warp; c < nchunks; c += nw) {
        int base = c * 8;
        float2 acc = make_float2(0.f, 0.f);
        int curb = batch[base];
        float cnt = 0.f;
        for (int i = 0; i < 8; i++) {
            int node = base + i;
            if (node >= N_NODES) break;
            int bb = batch[node];
            if (bb != curb) {
                red_add_v2(gsum + curb * H_DIM + 2 * lane, acc.x, acc.y);
                if (lane == 0) atomicAdd(&gcnt[curb], cnt);
                acc = make_float2(0.f, 0.f);
                cnt = 0.f;
                curb = bb;
            }
            float2 v = *(const float2*)(t + (size_t)node * H_DIM + 2 * lane);
            acc.x += v.x; acc.y += v.y;
            cnt += 1.f;
        }
        red_add_v2(gsum + curb * H_DIM + 2 * lane, acc.x, acc.y);
        if (lane == 0) atomicAdd(&gcnt[curb], cnt);
    }
}

// ---------------- final: fold layer1 w2 + output MLP ---------------------------
__global__ void final_kernel(const float* __restrict__ gsum,
                             const float* __restrict__ gcnt,
                             const float* __restrict__ nw2,   // (64,128) layer1
                             const float* __restrict__ nb2,   // (128,)
                             const float* __restrict__ w1,
                             const float* __restrict__ b1,
                             const float* __restrict__ w2,
                             const float* __restrict__ b2,
                             float* __restrict__ out) {
    int g = blockIdx.x;
    int tx = threadIdx.x;  // 128 threads
    __shared__ float sm64[H_DIM];
    __shared__ float sg[HID];
    __shared__ float st[HID];
    float cnt = fmaxf(gcnt[g], 1.0f);
    if (tx < H_DIM) sm64[tx] = gsum[g * H_DIM + tx] / cnt;   // mean(t)
    __syncthreads();
    // g_hid = relu(mean(t) @ nw2 + nb2)
    float gv = nb2[tx];
#pragma unroll 8
    for (int k = 0; k < H_DIM; k++) gv += sm64[k] * nw2[k * HID + tx];
    sg[tx] = fmaxf(gv, 0.0f);
    __syncthreads();
    float acc = b1[tx];
#pragma unroll 8
    for (int j = 0; j < HID; j++) acc += sg[j] * w1[j * HID + tx];
    st[tx] = fmaxf(acc, 0.0f);
    __syncthreads();
    if (tx < OUT_DIM) {
        float o = b2[tx];
#pragma unroll 8
        for (int k = 0; k < HID; k++) o += st[k] * w2[k * OUT_DIM + tx];
        out[g * OUT_DIM + tx] = o;
    }
}

// ---------------- launch --------------------------------------------------------
extern "C" void kernel_launch(void* const* d_in, const int* in_sizes, int n_in,
                              void* d_out, int out_size) {
    const float* x         = (const float*)d_in[0];
    const float* pos       = (const float*)d_in[1];
    const float* edge_attr = (const float*)d_in[2];
    const int* eidx        = (const int*)d_in[3];
    const int* batch       = (const int*)d_in[4];

    const float* mlp_w[2]  = {(const float*)d_in[5],  (const float*)d_in[14]};
    const float* edge_w[2] = {(const float*)d_in[6],  (const float*)d_in[15]};
    const float* edge_b[2] = {(const float*)d_in[7],  (const float*)d_in[16]};
    const float* coord_w[2]= {(const float*)d_in[8],  (const float*)d_in[17]};
    const float* coord_b[2]= {(const float*)d_in[9],  (const float*)d_in[18]};
    const float* nw1[2]    = {(const float*)d_in[10], (const float*)d_in[19]};
    const float* nb1[2]    = {(const float*)d_in[11], (const float*)d_in[20]};
    const float* nw2[2]    = {(const float*)d_in[12], (const float*)d_in[21]};
    const float* nb2[2]    = {(const float*)d_in[13], (const float*)d_in[22]};
    const float* ow1 = (const float*)d_in[23];
    const float* ob1 = (const float*)d_in[24];
    const float* ow2 = (const float*)d_in[25];
    const float* ob2 = (const float*)d_in[26];
    float* out = (float*)d_out;

    float *pa, *pb, *pe, *pt, *pc, *pd, *px1, *ppos, *pgs, *pgc;
    cudaGetSymbolAddress((void**)&pa, g_a);
    cudaGetSymbolAddress((void**)&pb, g_b);
    cudaGetSymbolAddress((void**)&pe, g_eagg);
    cudaGetSymbolAddress((void**)&pt, g_t);
    cudaGetSymbolAddress((void**)&pc, g_cusum);
    cudaGetSymbolAddress((void**)&pd, g_deg);
    cudaGetSymbolAddress((void**)&px1, g_x1);
    cudaGetSymbolAddress((void**)&ppos, g_pos1);
    cudaGetSymbolAddress((void**)&pgs, g_gsum);
    cudaGetSymbolAddress((void**)&pgc, g_gcnt);

    const int PRE_SMEM  = 2 * F_IN * H_DIM * (int)sizeof(float);                        // 64KB
    const int N1_SMEM   = (F_IN + H_DIM) * H_DIM * (int)sizeof(float);                  // 48KB
    const int EDGE_SMEM = (H_DIM*H_DIM + D_ATTR*H_DIM + 8*EPG*2*H_DIM) * (int)sizeof(float); // 52KB
    cudaFuncSetAttribute(precompute_ab, cudaFuncAttributeMaxDynamicSharedMemorySize, PRE_SMEM);
    cudaFuncSetAttribute(node1_kernel, cudaFuncAttributeMaxDynamicSharedMemorySize, N1_SMEM);
    cudaFuncSetAttribute(edge_kernel, cudaFuncAttributeMaxDynamicSharedMemorySize, EDGE_SMEM);

    for (int l = 0; l < 2; l++) {
        const float* xin   = l ? px1 : x;
        const float* posin = l ? ppos : pos;
        cudaMemsetAsync(pe, 0, (size_t)N_NODES * H_DIM * sizeof(float));
        if (l == 0) {
            cudaMemsetAsync(pc, 0, (size_t)N_NODES * 3 * sizeof(float));
            cudaMemsetAsync(pd, 0, (size_t)N_NODES * sizeof(float));
        }
        precompute_ab<<<444, 256, PRE_SMEM>>>(xin, mlp_w[l], pa, pb);
        edge_kernel<<<592, 256, EDGE_SMEM>>>(posin, eidx, edge_attr, mlp_w[l],
                                             edge_w[l], edge_b[l], coord_w[l], coord_b[l],
                                             pa, pb, pe, pc, pd, l == 0 ? 1 : 0);
        node1_kernel<<<592, 256, N1_SMEM>>>(xin, pe, nw1[l], nb1[l], pt);
        if (l == 0)
            node2_kernel<<<444, 256>>>(pt, nw2[0], nb2[0], posin, pc, pd, px1, ppos);
    }

    cudaMemsetAsync(pgs, 0, (size_t)G_GRAPHS * H_DIM * sizeof(float));
    cudaMemsetAsync(pgc, 0, (size_t)G_GRAPHS * sizeof(float));
    pool_kernel<<<64, 256>>>(pt, batch, pgs, pgc);
    final_kernel<<<G_GRAPHS, HID>>>(pgs, pgc, nw2[1], nb2[1], ow1, ob1, ow2, ob2, out);
}

// round 5
// speedup vs baseline: 1.9044x; 1.2107x over previous
#include <cuda_runtime.h>

typedef unsigned long long ull;

#define N_NODES 25000
#define N_EDGES 400000
#define F_IN    128
#define D_ATTR  16
#define H_DIM   64
#define HID     128
#define OUT_DIM 32
#define G_GRAPHS 64
#define EPG     8

// ---------------- scratch (device globals) -----------------------------------
__device__ float g_a[N_NODES * H_DIM];
__device__ float g_b[N_NODES * H_DIM];
__device__ float g_eagg[N_NODES * H_DIM];
__device__ float g_t[N_NODES * H_DIM];
__device__ float g_cusum[N_NODES * 3];
__device__ float g_deg[N_NODES];
__device__ float g_x1[N_NODES * HID];
__device__ float g_pos1[N_NODES * 3];
__device__ float g_gsum[G_GRAPHS * H_DIM];
__device__ float g_gcnt[G_GRAPHS];

// ---------------- packed f32x2 helpers (sm_103a FFMA2) -----------------------
__device__ __forceinline__ ull fma2(ull a, ull b, ull c) {
    ull d;
    asm("fma.rn.f32x2 %0, %1, %2, %3;" : "=l"(d) : "l"(a), "l"(b), "l"(c));
    return d;
}
__device__ __forceinline__ ull pack2(float x, float y) {
    ull r; asm("mov.b64 %0, {%1, %2};" : "=l"(r) : "f"(x), "f"(y)); return r;
}
__device__ __forceinline__ float2 unpack2(ull v) {
    float lo, hi; asm("mov.b64 {%0, %1}, %2;" : "=f"(lo), "=f"(hi) : "l"(v));
    return make_float2(lo, hi);
}
__device__ __forceinline__ void red_add_v2(float* a, float x, float y) {
    asm volatile("red.global.add.v2.f32 [%0], {%1, %2};"
                 :: "l"(a), "f"(x), "f"(y) : "memory");
}
// silu via single-MUFU tanh: v*sigmoid(v) = 0.5*v*(1+tanh(v/2))
__device__ __forceinline__ float silu_f(float v) {
    float t;
    asm("tanh.approx.f32 %0, %1;" : "=f"(t) : "f"(0.5f * v));
    float hv = 0.5f * v;
    return fmaf(hv, t, hv);
}

// ---------------- precompute: a = x@W_dst, b = x@W_src (4 nodes/warp) --------
// mlp_w (273,64): rows [0,128)=W_dst, [128,256)=W_src, [256,272)=W_attr, 272=w_rad
// k-packed prepacked weights: swp[kp*64 + c] = (W[2kp][c], W[2kp+1][c])
__global__ void __launch_bounds__(256, 3) precompute_ab(const float* __restrict__ x,
                                                        const float* __restrict__ mlp_w,
                                                        float* __restrict__ a,
                                                        float* __restrict__ b) {
    extern __shared__ ull swp[];                  // 8192 ull = 64KB: [0,4096)=Wd, [4096,8192)=Ws
    for (int i = threadIdx.x; i < 4096; i += 256) {
        int kp = i >> 6, c = i & 63;
        swp[i]        = pack2(mlp_w[(2 * kp) * H_DIM + c],       mlp_w[(2 * kp + 1) * H_DIM + c]);
        swp[4096 + i] = pack2(mlp_w[(256 + 2 * kp) * H_DIM + c] - mlp_w[(256 + 2 * kp) * H_DIM + c]
                              + mlp_w[(128 + 2 * kp) * H_DIM + c],
                              mlp_w[(128 + 2 * kp + 1) * H_DIM + c]);
    }
    __syncthreads();

    int lane = threadIdx.x & 31;
    int warp = (blockIdx.x * 256 + threadIdx.x) >> 5;
    int nw = gridDim.x * 8;
    const int NG = N_NODES / 4;                   // 6250
    const ull* s_wd = swp;
    const ull* s_ws = swp + 4096;

    for (int g = warp; g < NG; g += nw) {
        int nbase = g * 4;
        ull aC0[4], aC1[4], bC0[4], bC1[4];
#pragma unroll
        for (int t = 0; t < 4; t++) { aC0[t]=0; aC1[t]=0; bC0[t]=0; bC1[t]=0; }
#pragma unroll 8
        for (int q = 0; q < 32; q++) {            // kpairs 2q, 2q+1
            ulonglong2 wd0 = *(const ulonglong2*)(s_wd + (2*q)   * 64 + 2*lane);
            ulonglong2 wd1 = *(const ulonglong2*)(s_wd + (2*q+1) * 64 + 2*lane);
            ulonglong2 ws0 = *(const ulonglong2*)(s_ws + (2*q)   * 64 + 2*lane);
            ulonglong2 ws1 = *(const ulonglong2*)(s_ws + (2*q+1) * 64 + 2*lane);
#pragma unroll
            for (int t = 0; t < 4; t++) {
                ulonglong2 xp = *(const ulonglong2*)(x + (size_t)(nbase + t) * F_IN + 4 * q);
                aC0[t] = fma2(xp.x, wd0.x, aC0[t]); aC1[t] = fma2(xp.x, wd0.y, aC1[t]);
                aC0[t] = fma2(xp.y, wd1.x, aC0[t]); aC1[t] = fma2(xp.y, wd1.y, aC1[t]);
                bC0[t] = fma2(xp.x, ws0.x, bC0[t]); bC1[t] = fma2(xp.x, ws0.y, bC1[t]);
                bC0[t] = fma2(xp.y, ws1.x, bC0[t]); bC1[t] = fma2(xp.y, ws1.y, bC1[t]);
            }
        }
#pragma unroll
        for (int t = 0; t < 4; t++) {
            float2 va0 = unpack2(aC0[t]), va1 = unpack2(aC1[t]);
            float2 vb0 = unpack2(bC0[t]), vb1 = unpack2(bC1[t]);
            *(float2*)(a + (size_t)(nbase + t) * H_DIM + 2*lane) =
                make_float2(va0.x + va0.y, va1.x + va1.y);
            *(float2*)(b + (size_t)(nbase + t) * H_DIM + 2*lane) =
                make_float2(vb0.x + vb0.y, vb1.x + vb1.y);
        }
    }
}

// ---------------- edge kernel: 8 edges/warp, fully k-packed -------------------
__global__ void __launch_bounds__(256, 3) edge_kernel(const float* __restrict__ pos,
                                                      const int* __restrict__ eidx,
                                                      const float* __restrict__ edge_attr,
                                                      const float* __restrict__ mlp_w,
                                                      const float* __restrict__ edge_w,
                                                      const float* __restrict__ edge_b,
                                                      const float* __restrict__ coord_w,
                                                      const float* __restrict__ coord_b,
                                                      const float* __restrict__ a,
                                                      const float* __restrict__ b,
                                                      float* __restrict__ eagg,
                                                      float* __restrict__ cusum,
                                                      float* __restrict__ deg,
                                                      int do_coord) {
    extern __shared__ ull sm_u[];
    ull* s_wp     = sm_u;                          // 2048 ull: edge_w kpacked
    ull* s_wattrP = sm_u + 2048;                   // 512 ull: W_attr kpacked
    float* s_hall = (float*)(sm_u + 2560);         // 8 warps * EPG*64 floats

    for (int i = threadIdx.x; i < 2048; i += 256) {
        int kp = i >> 6, c = i & 63;
        s_wp[i] = pack2(edge_w[(2 * kp) * H_DIM + c], edge_w[(2 * kp + 1) * H_DIM + c]);
    }
    {
        const float* wa = mlp_w + 2 * F_IN * H_DIM;
        for (int i = threadIdx.x; i < 512; i += 256) {
            int dp = i >> 6, c = i & 63;
            s_wattrP[i] = pack2(wa[(2 * dp) * H_DIM + c], wa[(2 * dp + 1) * H_DIM + c]);
        }
    }
    __syncthreads();

    int lane = threadIdx.x & 31, k0 = lane * 2;
    int wl = threadIdx.x >> 5;
    int warp = (blockIdx.x * 256 + threadIdx.x) >> 5;
    int nw = gridDim.x * 8;
    float* s_h = s_hall + wl * (EPG * H_DIM);

    float wr0 = mlp_w[(2 * F_IN + D_ATTR) * H_DIM + k0];
    float wr1 = mlp_w[(2 * F_IN + D_ATTR) * H_DIM + k0 + 1];
    float eb0 = edge_b[k0], eb1 = edge_b[k0 + 1];
    float cw0 = coord_w[k0], cw1 = coord_w[k0 + 1];
    float cb = coord_b[0];

    const int NGROUPS = N_EDGES / EPG;             // 50000
    for (int g = warp; g < NGROUPS; g += nw) {
        int ebase = g * EPG;
        int4 sa = *(const int4*)(eidx + ebase);
        int4 sb = *(const int4*)(eidx + ebase + 4);
        int4 da = *(const int4*)(eidx + N_EDGES + ebase);
        int4 db = *(const int4*)(eidx + N_EDGES + ebase + 4);
        int srcs[EPG] = {sa.x, sa.y, sa.z, sa.w, sb.x, sb.y, sb.z, sb.w};
        int dsts[EPG] = {da.x, da.y, da.z, da.w, db.x, db.y, db.z, db.w};
        float mydx = 0.f, mydy = 0.f, mydz = 0.f;   // lane t holds edge t's diff

        // ---- phase 1: per-edge h, in 2 batches of 4 (bounds registers)
#pragma unroll
        for (int half = 0; half < 2; half++) {
            float b0[4], b1[4];
            ull hk0[4], hk1[4];
#pragma unroll
            for (int t = 0; t < 4; t++) {
                int ei = half * 4 + t;
                int src = srcs[ei], dst = dsts[ei];
                float dx = pos[dst * 3 + 0] - pos[src * 3 + 0];
                float dy = pos[dst * 3 + 1] - pos[src * 3 + 1];
                float dz = pos[dst * 3 + 2] - pos[src * 3 + 2];
                if (lane == ei) { mydx = dx; mydy = dy; mydz = dz; }
                float radial = dx * dx + dy * dy + dz * dz;
                float2 av = *(const float2*)(a + (size_t)dst * H_DIM + k0);
                float2 bv = *(const float2*)(b + (size_t)src * H_DIM + k0);
                b0[t] = av.x + bv.x + radial * wr0;
                b1[t] = av.y + bv.y + radial * wr1;
                hk0[t] = 0; hk1[t] = 0;
            }
#pragma unroll
            for (int q = 0; q < 2; q++) {          // dpairs 4q..4q+3
                ulonglong2 w0 = *(const ulonglong2*)(s_wattrP + (4*q+0)*64 + 2*lane);
                ulonglong2 w1 = *(const ulonglong2*)(s_wattrP + (4*q+1)*64 + 2*lane);
                ulonglong2 w2 = *(const ulonglong2*)(s_wattrP + (4*q+2)*64 + 2*lane);
                ulonglong2 w3 = *(const ulonglong2*)(s_wattrP + (4*q+3)*64 + 2*lane);
#pragma unroll
                for (int t = 0; t < 4; t++) {
                    int e = ebase + half * 4 + t;
                    ulonglong2 eaA = *(const ulonglong2*)(edge_attr + (size_t)e * D_ATTR + 8*q);
                    ulonglong2 eaB = *(const ulonglong2*)(edge_attr + (size_t)e * D_ATTR + 8*q + 4);
                    hk0[t] = fma2(eaA.x, w0.x, hk0[t]); hk1[t] = fma2(eaA.x, w0.y, hk1[t]);
                    hk0[t] = fma2(eaA.y, w1.x, hk0[t]); hk1[t] = fma2(eaA.y, w1.y, hk1[t]);
                    hk0[t] = fma2(eaB.x, w2.x, hk0[t]); hk1[t] = fma2(eaB.x, w2.y, hk1[t]);
                    hk0[t] = fma2(eaB.y, w3.x, hk0[t]); hk1[t] = fma2(eaB.y, w3.y, hk1[t]);
                }
            }
#pragma unroll
            for (int t = 0; t < 4; t++) {
                float2 v0 = unpack2(hk0[t]), v1 = unpack2(hk1[t]);
                float h0 = silu_f(b0[t] + v0.x + v0.y);
                float h1 = silu_f(b1[t] + v1.x + v1.y);
                *(float2*)(s_h + (half * 4 + t) * H_DIM + k0) = make_float2(h0, h1);
            }
        }
        __syncwarp();

        // ---- phase 2: e = silu(h @ edge_w + eb), k-packed
        ull acc0[EPG], acc1[EPG];
#pragma unroll
        for (int t = 0; t < EPG; t++) { acc0[t] = 0; acc1[t] = 0; }
#pragma unroll 4
        for (int q = 0; q < 16; q++) {             // kpairs 2q, 2q+1 (k = 4q..4q+3)
            ulonglong2 wA = *(const ulonglong2*)(s_wp + (2*q)   * 64 + 2*lane);
            ulonglong2 wB = *(const ulonglong2*)(s_wp + (2*q+1) * 64 + 2*lane);
#pragma unroll
            for (int t = 0; t < EPG; t++) {
                ulonglong2 hv = *(const ulonglong2*)(s_h + t * H_DIM + 4 * q);
                acc0[t] = fma2(hv.x, wA.x, acc0[t]); acc1[t] = fma2(hv.x, wA.y, acc1[t]);
                acc0[t] = fma2(hv.y, wB.x, acc0[t]); acc1[t] = fma2(hv.y, wB.y, acc1[t]);
            }
        }
        __syncwarp();

        // ---- epilogue
        float myss = 0.f;
#pragma unroll
        for (int t = 0; t < EPG; t++) {
            float2 v0 = unpack2(acc0[t]), v1 = unpack2(acc1[t]);
            float e0 = silu_f(eb0 + v0.x + v0.y);
            float e1 = silu_f(eb1 + v1.x + v1.y);
            red_add_v2(eagg + (size_t)dsts[t] * H_DIM + k0, e0, e1);
            if (do_coord) {
                float p = e0 * cw0 + e1 * cw1;
                p += __shfl_xor_sync(0xffffffffu, p, 16);
                p += __shfl_xor_sync(0xffffffffu, p, 8);
                p += __shfl_xor_sync(0xffffffffu, p, 4);
                p += __shfl_xor_sync(0xffffffffu, p, 2);
                p += __shfl_xor_sync(0xffffffffu, p, 1);
                if (lane == t) myss = silu_f(p + cb);
            }
        }
        if (do_coord && lane < EPG) {
            int d3 = dsts[lane] * 3;
            atomicAdd(cusum + d3 + 0, mydx * myss);
            atomicAdd(cusum + d3 + 1, mydy * myss);
            atomicAdd(cusum + d3 + 2, mydz * myss);
            atomicAdd(deg + dsts[lane], 1.0f);
        }
    }
}

// ---------------- node stage 1: t = silu([x,eagg]@w1 + b1), 8 nodes/warp ------
__global__ void __launch_bounds__(256, 3) node1_kernel(const float* __restrict__ xin,
                                                       const float* __restrict__ eagg,
                                                       const float* __restrict__ nw1,
                                                       const float* __restrict__ nb1,
                                                       float* __restrict__ tout) {
    extern __shared__ ull s_w1p[];                 // 96 kpairs * 64 cols = 6144 ull = 48KB
    for (int i = threadIdx.x; i < 96 * 64; i += 256) {
        int kp = i >> 6, c = i & 63;
        s_w1p[i] = pack2(nw1[(2 * kp) * H_DIM + c], nw1[(2 * kp + 1) * H_DIM + c]);
    }
    __syncthreads();

    int lane = threadIdx.x & 31;
    int warp = (blockIdx.x * 256 + threadIdx.x) >> 5;
    int nw = gridDim.x * 8;
    float nb0 = nb1[2 * lane], nbx1 = nb1[2 * lane + 1];
    const int NG = N_NODES / 8;                    // 3125

    for (int g = warp; g < NG; g += nw) {
        int nbase = g * 8;
        ull a0[8], a1[8];
#pragma unroll
        for (int t = 0; t < 8; t++) { a0[t] = 0; a1[t] = 0; }
#pragma unroll 4
        for (int q = 0; q < 32; q++) {             // x part: kpairs 2q, 2q+1
            ulonglong2 w0 = *(const ulonglong2*)(s_w1p + (2*q)   * 64 + 2*lane);
            ulonglong2 w1 = *(const ulonglong2*)(s_w1p + (2*q+1) * 64 + 2*lane);
#pragma unroll
            for (int t = 0; t < 8; t++) {
                ulonglong2 xp = *(const ulonglong2*)(xin + (size_t)(nbase + t) * F_IN + 4 * q);
                a0[t] = fma2(xp.x, w0.x, a0[t]); a1[t] = fma2(xp.x, w0.y, a1[t]);
                a0[t] = fma2(xp.y, w1.x, a0[t]); a1[t] = fma2(xp.y, w1.y, a1[t]);
            }
        }
#pragma unroll 4
        for (int q = 0; q < 16; q++) {             // eagg part: kpairs 64+2q, 64+2q+1
            ulonglong2 w0 = *(const ulonglong2*)(s_w1p + (64 + 2*q)     * 64 + 2*lane);
            ulonglong2 w1 = *(const ulonglong2*)(s_w1p + (64 + 2*q + 1) * 64 + 2*lane);
#pragma unroll
            for (int t = 0; t < 8; t++) {
                ulonglong2 ep = *(const ulonglong2*)(eagg + (size_t)(nbase + t) * H_DIM + 4 * q);
                a0[t] = fma2(ep.x, w0.x, a0[t]); a1[t] = fma2(ep.x, w0.y, a1[t]);
                a0[t] = fma2(ep.y, w1.x, a0[t]); a1[t] = fma2(ep.y, w1.y, a1[t]);
            }
        }
#pragma unroll
        for (int t = 0; t < 8; t++) {
            float2 v0 = unpack2(a0[t]), v1 = unpack2(a1[t]);
            *(float2*)(tout + (size_t)(nbase + t) * H_DIM + 2*lane) =
                make_float2(silu_f(nb0 + v0.x + v0.y), silu_f(nbx1 + v1.x + v1.y));
        }
    }
}

// ---------------- node stage 2 (layer 0 only): x1 = t@w2 + b2, pos update -----
__global__ void __launch_bounds__(256, 3) node2_kernel(const float* __restrict__ tin,
                                                       const float* __restrict__ nw2,
                                                       const float* __restrict__ nb2,
                                                       const float* __restrict__ posin,
                                                       const float* __restrict__ cusum,
                                                       const float* __restrict__ deg,
                                                       float* __restrict__ xout,
                                                       float* __restrict__ posout) {
    extern __shared__ ull s_w2p[];                 // 32 kpairs * 128 cols = 4096 ull = 32KB
    for (int i = threadIdx.x; i < 32 * 128; i += 256) {
        int kp = i >> 7, c = i & 127;
        s_w2p[i] = pack2(nw2[(2 * kp) * HID + c], nw2[(2 * kp + 1) * HID + c]);
    }
    __syncthreads();

    int lane = threadIdx.x & 31;
    int warp = (blockIdx.x * 256 + threadIdx.x) >> 5;
    int nw = gridDim.x * 8;
    float bL0 = nb2[2*lane], bL1 = nb2[2*lane+1];
    float bH0 = nb2[H_DIM + 2*lane], bH1 = nb2[H_DIM + 2*lane+1];
    const int NG = N_NODES / 4;

    for (int g = warp; g < NG; g += nw) {
        int nbase = g * 4;
        ull aL0[4], aL1[4], aH0[4], aH1[4];
#pragma unroll
        for (int t = 0; t < 4; t++) { aL0[t]=0; aL1[t]=0; aH0[t]=0; aH1[t]=0; }
#pragma unroll 4
        for (int q = 0; q < 16; q++) {             // kpairs 2q, 2q+1
            ulonglong2 wL0 = *(const ulonglong2*)(s_w2p + (2*q)   * 128 + 2*lane);
            ulonglong2 wH0 = *(const ulonglong2*)(s_w2p + (2*q)   * 128 + 64 + 2*lane);
            ulonglong2 wL1 = *(const ulonglong2*)(s_w2p + (2*q+1) * 128 + 2*lane);
            ulonglong2 wH1 = *(const ulonglong2*)(s_w2p + (2*q+1) * 128 + 64 + 2*lane);
#pragma unroll
            for (int t = 0; t < 4; t++) {
                ulonglong2 tp = *(const ulonglong2*)(tin + (size_t)(nbase + t) * H_DIM + 4 * q);
                aL0[t] = fma2(tp.x, wL0.x, aL0[t]); aL1[t] = fma2(tp.x, wL0.y, aL1[t]);
                aH0[t] = fma2(tp.x, wH0.x, aH0[t]); aH1[t] = fma2(tp.x, wH0.y, aH1[t]);
                aL0[t] = fma2(tp.y, wL1.x, aL0[t]); aL1[t] = fma2(tp.y, wL1.y, aL1[t]);
                aH0[t] = fma2(tp.y, wH1.x, aH0[t]); aH1[t] = fma2(tp.y, wH1.y, aH1[t]);
            }
        }
#pragma unroll
        for (int t = 0; t < 4; t++) {
            float2 l0 = unpack2(aL0[t]), l1 = unpack2(aL1[t]);
            float2 h0 = unpack2(aH0[t]), h1 = unpack2(aH1[t]);
            *(float2*)(xout + (size_t)(nbase + t) * HID + 2*lane) =
                make_float2(bL0 + l0.x + l0.y, bL1 + l1.x + l1.y);
            *(float2*)(xout + (size_t)(nbase + t) * HID + H_DIM + 2*lane) =
                make_float2(bH0 + h0.x + h0.y, bH1 + h1.x + h1.y);
        }
        if (lane < 4) {
            int node = nbase + lane;
            float dg = fmaxf(deg[node], 1.0f);
            posout[node * 3 + 0] = posin[node * 3 + 0] + cusum[node * 3 + 0] / dg;
            posout[node * 3 + 1] = posin[node * 3 + 1] + cusum[node * 3 + 1] / dg;
            posout[node * 3 + 2] = posin[node * 3 + 2] + cusum[node * 3 + 2] / dg;
        }
    }
}

// ---------------- pooling of t (H=64), batch sorted ----------------------------
__global__ void pool_kernel(const float* __restrict__ t,
                            const int* __restrict__ batch,
                            float* __restrict__ gsum, float* __restrict__ gcnt) {
    int lane = threadIdx.x & 31;
    int warp = (blockIdx.x * blockDim.x + threadIdx.x) >> 5;
    int nw = (gridDim.x * blockDim.x) >> 5;
    int nchunks = (N_NODES + 7) / 8;

    for (int c = warp; c < nchunks; c += nw) {
        int base = c * 8;
        float2 acc = make_float2(0.f, 0.f);
        int curb = batch[base];
        float cnt = 0.f;
        for (int i = 0; i < 8; i++) {
            int node = base + i;
            if (node >= N_NODES) break;
            int bb = batch[node];
            if (bb != curb) {
                red_add_v2(gsum + curb * H_DIM + 2 * lane, acc.x, acc.y);
                if (lane == 0) atomicAdd(&gcnt[curb], cnt);
                acc = make_float2(0.f, 0.f);
                cnt = 0.f;
                curb = bb;
            }
            float2 v = *(const float2*)(t + (size_t)node * H_DIM + 2 * lane);
            acc.x += v.x; acc.y += v.y;
            cnt += 1.f;
        }
        red_add_v2(gsum + curb * H_DIM + 2 * lane, acc.x, acc.y);
        if (lane == 0) atomicAdd(&gcnt[curb], cnt);
    }
}

// ---------------- final: fold layer1 w2 + output MLP ---------------------------
__global__ void final_kernel(const float* __restrict__ gsum,
                             const float* __restrict__ gcnt,
                             const float* __restrict__ nw2,   // (64,128) layer1
                             const float* __restrict__ nb2,   // (128,)
                             const float* __restrict__ w1,
                             const float* __restrict__ b1,
                             const float* __restrict__ w2,
                             const float* __restrict__ b2,
                             float* __restrict__ out) {
    int g = blockIdx.x;
    int tx = threadIdx.x;  // 128 threads
    __shared__ float sm64[H_DIM];
    __shared__ float sg[HID];
    __shared__ float st[HID];
    float cnt = fmaxf(gcnt[g], 1.0f);
    if (tx < H_DIM) sm64[tx] = gsum[g * H_DIM + tx] / cnt;   // mean(t)
    __syncthreads();
    float gv = nb2[tx];
#pragma unroll 8
    for (int k = 0; k < H_DIM; k++) gv += sm64[k] * nw2[k * HID + tx];
    sg[tx] = fmaxf(gv, 0.0f);
    __syncthreads();
    float acc = b1[tx];
#pragma unroll 8
    for (int j = 0; j < HID; j++) acc += sg[j] * w1[j * HID + tx];
    st[tx] = fmaxf(acc, 0.0f);
    __syncthreads();
    if (tx < OUT_DIM) {
        float o = b2[tx];
#pragma unroll 8
        for (int k = 0; k < HID; k++) o += st[k] * w2[k * OUT_DIM + tx];
        out[g * OUT_DIM + tx] = o;
    }
}

// ---------------- launch --------------------------------------------------------
extern "C" void kernel_launch(void* const* d_in, const int* in_sizes, int n_in,
                              void* d_out, int out_size) {
    const float* x         = (const float*)d_in[0];
    const float* pos       = (const float*)d_in[1];
    const float* edge_attr = (const float*)d_in[2];
    const int* eidx        = (const int*)d_in[3];
    const int* batch       = (const int*)d_in[4];

    const float* mlp_w[2]  = {(const float*)d_in[5],  (const float*)d_in[14]};
    const float* edge_w[2] = {(const float*)d_in[6],  (const float*)d_in[15]};
    const float* edge_b[2] = {(const float*)d_in[7],  (const float*)d_in[16]};
    const float* coord_w[2]= {(const float*)d_in[8],  (const float*)d_in[17]};
    const float* coord_b[2]= {(const float*)d_in[9],  (const float*)d_in[18]};
    const float* nw1[2]    = {(const float*)d_in[10], (const float*)d_in[19]};
    const float* nb1[2]    = {(const float*)d_in[11], (const float*)d_in[20]};
    const float* nw2[2]    = {(const float*)d_in[12], (const float*)d_in[21]};
    const float* nb2[2]    = {(const float*)d_in[13], (const float*)d_in[22]};
    const float* ow1 = (const float*)d_in[23];
    const float* ob1 = (const float*)d_in[24];
    const float* ow2 = (const float*)d_in[25];
    const float* ob2 = (const float*)d_in[26];
    float* out = (float*)d_out;

    float *pa, *pb, *pe, *pt, *pc, *pd, *px1, *ppos, *pgs, *pgc;
    cudaGetSymbolAddress((void**)&pa, g_a);
    cudaGetSymbolAddress((void**)&pb, g_b);
    cudaGetSymbolAddress((void**)&pe, g_eagg);
    cudaGetSymbolAddress((void**)&pt, g_t);
    cudaGetSymbolAddress((void**)&pc, g_cusum);
    cudaGetSymbolAddress((void**)&pd, g_deg);
    cudaGetSymbolAddress((void**)&px1, g_x1);
    cudaGetSymbolAddress((void**)&ppos, g_pos1);
    cudaGetSymbolAddress((void**)&pgs, g_gsum);
    cudaGetSymbolAddress((void**)&pgc, g_gcnt);

    const int PRE_SMEM  = 8192 * (int)sizeof(ull);                         // 64KB
    const int N1_SMEM   = 96 * 64 * (int)sizeof(ull);                      // 48KB
    const int N2_SMEM   = 32 * 128 * (int)sizeof(ull);                     // 32KB
    const int EDGE_SMEM = 2560 * (int)sizeof(ull) + 8 * EPG * H_DIM * (int)sizeof(float); // 36KB
    cudaFuncSetAttribute(precompute_ab, cudaFuncAttributeMaxDynamicSharedMemorySize, PRE_SMEM);
    cudaFuncSetAttribute(node1_kernel, cudaFuncAttributeMaxDynamicSharedMemorySize, N1_SMEM);
    cudaFuncSetAttribute(node2_kernel, cudaFuncAttributeMaxDynamicSharedMemorySize, N2_SMEM);
    cudaFuncSetAttribute(edge_kernel, cudaFuncAttributeMaxDynamicSharedMemorySize, EDGE_SMEM);

    for (int l = 0; l < 2; l++) {
        const float* xin   = l ? px1 : x;
        const float* posin = l ? ppos : pos;
        cudaMemsetAsync(pe, 0, (size_t)N_NODES * H_DIM * sizeof(float));
        if (l == 0) {
            cudaMemsetAsync(pc, 0, (size_t)N_NODES * 3 * sizeof(float));
            cudaMemsetAsync(pd, 0, (size_t)N_NODES * sizeof(float));
        }
        precompute_ab<<<444, 256, PRE_SMEM>>>(xin, mlp_w[l], pa, pb);
        edge_kernel<<<740, 256, EDGE_SMEM>>>(posin, eidx, edge_attr, mlp_w[l],
                                             edge_w[l], edge_b[l], coord_w[l], coord_b[l],
                                             pa, pb, pe, pc, pd, l == 0 ? 1 : 0);
        node1_kernel<<<592, 256, N1_SMEM>>>(xin, pe, nw1[l], nb1[l], pt);
        if (l == 0)
            node2_kernel<<<444, 256, N2_SMEM>>>(pt, nw2[0], nb2[0], posin, pc, pd, px1, ppos);
    }

    cudaMemsetAsync(pgs, 0, (size_t)G_GRAPHS * H_DIM * sizeof(float));
    cudaMemsetAsync(pgc, 0, (size_t)G_GRAPHS * sizeof(float));
    pool_kernel<<<64, 256>>>(pt, batch, pgs, pgc);
    final_kernel<<<G_GRAPHS, HID>>>(pgs, pgc, nw2[1], nb2[1], ow1, ob1, ow2, ob2, out);
}

// round 6
// speedup vs baseline: 2.2823x; 1.1984x over previous
#include <cuda_runtime.h>

typedef unsigned long long ull;

#define N_NODES 25000
#define N_EDGES 400000
#define F_IN    128
#define D_ATTR  16
#define H_DIM   64
#define HID     128
#define OUT_DIM 32
#define G_GRAPHS 64
#define EPG     8

// ---------------- scratch (device globals) -----------------------------------
__device__ float g_a[N_NODES * H_DIM];
__device__ float g_b[N_NODES * H_DIM];
__device__ float g_eagg[N_NODES * H_DIM];
__device__ float g_t[N_NODES * H_DIM];
__device__ float g_t2[N_NODES * H_DIM];
__device__ float g_cusum[N_NODES * 3];
__device__ float g_deg[N_NODES];
__device__ float g_pos1[N_NODES * 3];
__device__ float g_gsum[G_GRAPHS * H_DIM];
__device__ float g_gcnt[G_GRAPHS];
__device__ float g_fold[3 * 65 * H_DIM];   // A1 | B1 | Wnx, each 65x64 (row 64 = bias)

// ---------------- packed f32x2 helpers (sm_103a FFMA2) -----------------------
__device__ __forceinline__ ull fma2(ull a, ull b, ull c) {
    ull d;
    asm("fma.rn.f32x2 %0, %1, %2, %3;" : "=l"(d) : "l"(a), "l"(b), "l"(c));
    return d;
}
__device__ __forceinline__ ull pack2(float x, float y) {
    ull r; asm("mov.b64 %0, {%1, %2};" : "=l"(r) : "f"(x), "f"(y)); return r;
}
__device__ __forceinline__ float2 unpack2(ull v) {
    float lo, hi; asm("mov.b64 {%0, %1}, %2;" : "=f"(lo), "=f"(hi) : "l"(v));
    return make_float2(lo, hi);
}
__device__ __forceinline__ void red_add_v2(float* a, float x, float y) {
    asm volatile("red.global.add.v2.f32 [%0], {%1, %2};"
                 :: "l"(a), "f"(x), "f"(y) : "memory");
}
// silu via single-MUFU tanh: v*sigmoid(v) = 0.5*v*(1+tanh(v/2))
__device__ __forceinline__ float silu_f(float v) {
    float t;
    asm("tanh.approx.f32 %0, %1;" : "=f"(t) : "f"(0.5f * v));
    float hv = 0.5f * v;
    return fmaf(hv, t, hv);
}

// ---------------- fold prep: A1=W2@W1d, B1=W2@W1s, Wnx=W2@nw1x (+bias rows) ---
__global__ void prep_fold(const float* __restrict__ nw2_0,   // (64,128)
                          const float* __restrict__ nb2_0,   // (128)
                          const float* __restrict__ mlp_w1,  // (273,64)
                          const float* __restrict__ nw1_1,   // (192,64)
                          float* __restrict__ fold) {
    int m = blockIdx.y;                      // 0:A1 1:B1 2:Wnx
    const float* W = (m == 0) ? mlp_w1 : (m == 1) ? (mlp_w1 + 128 * H_DIM) : nw1_1;
    int row = blockIdx.x;                    // 0..64 (64 = bias)
    int c = threadIdx.x;                     // 0..63
    float s = 0.f;
    if (row < 64) {
#pragma unroll 8
        for (int j = 0; j < 128; j++) s += nw2_0[row * HID + j] * W[j * H_DIM + c];
    } else {
#pragma unroll 8
        for (int j = 0; j < 128; j++) s += nb2_0[j] * W[j * H_DIM + c];
    }
    fold[(m * 65 + row) * H_DIM + c] = s;
}

// ---------------- layer-0 precompute: a = x@W_dst, b = x@W_src ---------------
__global__ void __launch_bounds__(256, 3) precompute_ab(const float* __restrict__ x,
                                                        const float* __restrict__ mlp_w,
                                                        float* __restrict__ a,
                                                        float* __restrict__ b) {
    extern __shared__ ull swp[];                  // 8192 ull = 64KB
    for (int i = threadIdx.x; i < 4096; i += 256) {
        int kp = i >> 6, c = i & 63;
        swp[i]        = pack2(mlp_w[(2 * kp) * H_DIM + c], mlp_w[(2 * kp + 1) * H_DIM + c]);
        swp[4096 + i] = pack2(mlp_w[(128 + 2 * kp) * H_DIM + c],
                              mlp_w[(128 + 2 * kp + 1) * H_DIM + c]);
    }
    __syncthreads();

    int lane = threadIdx.x & 31;
    int warp = (blockIdx.x * 256 + threadIdx.x) >> 5;
    int nw = gridDim.x * 8;
    const int NG = N_NODES / 4;                   // 6250
    const ull* s_wd = swp;
    const ull* s_ws = swp + 4096;

    for (int g = warp; g < NG; g += nw) {
        int nbase = g * 4;
        ull aC0[4], aC1[4], bC0[4], bC1[4];
#pragma unroll
        for (int t = 0; t < 4; t++) { aC0[t]=0; aC1[t]=0; bC0[t]=0; bC1[t]=0; }
#pragma unroll 8
        for (int q = 0; q < 32; q++) {
            ulonglong2 wd0 = *(const ulonglong2*)(s_wd + (2*q)   * 64 + 2*lane);
            ulonglong2 wd1 = *(const ulonglong2*)(s_wd + (2*q+1) * 64 + 2*lane);
            ulonglong2 ws0 = *(const ulonglong2*)(s_ws + (2*q)   * 64 + 2*lane);
            ulonglong2 ws1 = *(const ulonglong2*)(s_ws + (2*q+1) * 64 + 2*lane);
#pragma unroll
            for (int t = 0; t < 4; t++) {
                ulonglong2 xp = *(const ulonglong2*)(x + (size_t)(nbase + t) * F_IN + 4 * q);
                aC0[t] = fma2(xp.x, wd0.x, aC0[t]); aC1[t] = fma2(xp.x, wd0.y, aC1[t]);
                aC0[t] = fma2(xp.y, wd1.x, aC0[t]); aC1[t] = fma2(xp.y, wd1.y, aC1[t]);
                bC0[t] = fma2(xp.x, ws0.x, bC0[t]); bC1[t] = fma2(xp.x, ws0.y, bC1[t]);
                bC0[t] = fma2(xp.y, ws1.x, bC0[t]); bC1[t] = fma2(xp.y, ws1.y, bC1[t]);
            }
        }
#pragma unroll
        for (int t = 0; t < 4; t++) {
            float2 va0 = unpack2(aC0[t]), va1 = unpack2(aC1[t]);
            float2 vb0 = unpack2(bC0[t]), vb1 = unpack2(bC1[t]);
            *(float2*)(a + (size_t)(nbase + t) * H_DIM + 2*lane) =
                make_float2(va0.x + va0.y, va1.x + va1.y);
            *(float2*)(b + (size_t)(nbase + t) * H_DIM + 2*lane) =
                make_float2(vb0.x + vb0.y, vb1.x + vb1.y);
        }
    }
}

// ---------------- layer-1 fused precompute: a1=t@A1+ba, b1=t@B1+bb, pos -------
__global__ void __launch_bounds__(256, 3) precompute_t(const float* __restrict__ tin,
                                                       const float* __restrict__ fold,
                                                       const float* __restrict__ posin,
                                                       const float* __restrict__ cusum,
                                                       const float* __restrict__ deg,
                                                       float* __restrict__ a,
                                                       float* __restrict__ b,
                                                       float* __restrict__ posout) {
    extern __shared__ ull swp[];                  // 4096 ull = 32KB: A1 | B1 kpacked
    for (int i = threadIdx.x; i < 2048; i += 256) {
        int kp = i >> 6, c = i & 63;
        swp[i]        = pack2(fold[(2 * kp) * H_DIM + c], fold[(2 * kp + 1) * H_DIM + c]);
        swp[2048 + i] = pack2(fold[(65 + 2 * kp) * H_DIM + c],
                              fold[(65 + 2 * kp + 1) * H_DIM + c]);
    }
    __syncthreads();

    int lane = threadIdx.x & 31;
    int warp = (blockIdx.x * 256 + threadIdx.x) >> 5;
    int nw = gridDim.x * 8;
    float ba0 = fold[64 * H_DIM + 2*lane],        ba1 = fold[64 * H_DIM + 2*lane + 1];
    float bb0 = fold[(65 + 64) * H_DIM + 2*lane], bb1 = fold[(65 + 64) * H_DIM + 2*lane + 1];
    const int NG = N_NODES / 4;

    for (int g = warp; g < NG; g += nw) {
        int nbase = g * 4;
        ull aC0[4], aC1[4], bC0[4], bC1[4];
#pragma unroll
        for (int t = 0; t < 4; t++) { aC0[t]=0; aC1[t]=0; bC0[t]=0; bC1[t]=0; }
#pragma unroll 4
        for (int q = 0; q < 16; q++) {            // K=64: kpairs 2q, 2q+1
            ulonglong2 wa0 = *(const ulonglong2*)(swp + (2*q)   * 64 + 2*lane);
            ulonglong2 wa1 = *(const ulonglong2*)(swp + (2*q+1) * 64 + 2*lane);
            ulonglong2 wb0 = *(const ulonglong2*)(swp + 2048 + (2*q)   * 64 + 2*lane);
            ulonglong2 wb1 = *(const ulonglong2*)(swp + 2048 + (2*q+1) * 64 + 2*lane);
#pragma unroll
            for (int t = 0; t < 4; t++) {
                ulonglong2 tp = *(const ulonglong2*)(tin + (size_t)(nbase + t) * H_DIM + 4 * q);
                aC0[t] = fma2(tp.x, wa0.x, aC0[t]); aC1[t] = fma2(tp.x, wa0.y, aC1[t]);
                aC0[t] = fma2(tp.y, wa1.x, aC0[t]); aC1[t] = fma2(tp.y, wa1.y, aC1[t]);
                bC0[t] = fma2(tp.x, wb0.x, bC0[t]); bC1[t] = fma2(tp.x, wb0.y, bC1[t]);
                bC0[t] = fma2(tp.y, wb1.x, bC0[t]); bC1[t] = fma2(tp.y, wb1.y, bC1[t]);
            }
        }
#pragma unroll
        for (int t = 0; t < 4; t++) {
            float2 va0 = unpack2(aC0[t]), va1 = unpack2(aC1[t]);
            float2 vb0 = unpack2(bC0[t]), vb1 = unpack2(bC1[t]);
            *(float2*)(a + (size_t)(nbase + t) * H_DIM + 2*lane) =
                make_float2(ba0 + va0.x + va0.y, ba1 + va1.x + va1.y);
            *(float2*)(b + (size_t)(nbase + t) * H_DIM + 2*lane) =
                make_float2(bb0 + vb0.x + vb0.y, bb1 + vb1.x + vb1.y);
        }
        if (lane < 4) {
            int node = nbase + lane;
            float dg = fmaxf(deg[node], 1.0f);
            posout[node * 3 + 0] = posin[node * 3 + 0] + cusum[node * 3 + 0] / dg;
            posout[node * 3 + 1] = posin[node * 3 + 1] + cusum[node * 3 + 1] / dg;
            posout[node * 3 + 2] = posin[node * 3 + 2] + cusum[node * 3 + 2] / dg;
        }
    }
}

// ---------------- edge kernel: 8 edges/warp, fully k-packed -------------------
__global__ void __launch_bounds__(256, 3) edge_kernel(const float* __restrict__ pos,
                                                      const int* __restrict__ eidx,
                                                      const float* __restrict__ edge_attr,
                                                      const float* __restrict__ mlp_w,
                                                      const float* __restrict__ edge_w,
                                                      const float* __restrict__ edge_b,
                                                      const float* __restrict__ coord_w,
                                                      const float* __restrict__ coord_b,
                                                      const float* __restrict__ a,
                                                      const float* __restrict__ b,
                                                      float* __restrict__ eagg,
                                                      float* __restrict__ cusum,
                                                      float* __restrict__ deg,
                                                      int do_coord) {
    extern __shared__ ull sm_u[];
    ull* s_wp     = sm_u;                          // 2048 ull: edge_w kpacked
    ull* s_wattrP = sm_u + 2048;                   // 512 ull: W_attr kpacked
    float* s_hall = (float*)(sm_u + 2560);         // 8 warps * EPG*64 floats

    for (int i = threadIdx.x; i < 2048; i += 256) {
        int kp = i >> 6, c = i & 63;
        s_wp[i] = pack2(edge_w[(2 * kp) * H_DIM + c], edge_w[(2 * kp + 1) * H_DIM + c]);
    }
    {
        const float* wa = mlp_w + 2 * F_IN * H_DIM;
        for (int i = threadIdx.x; i < 512; i += 256) {
            int dp = i >> 6, c = i & 63;
            s_wattrP[i] = pack2(wa[(2 * dp) * H_DIM + c], wa[(2 * dp + 1) * H_DIM + c]);
        }
    }
    __syncthreads();

    int lane = threadIdx.x & 31, k0 = lane * 2;
    int wl = threadIdx.x >> 5;
    int warp = (blockIdx.x * 256 + threadIdx.x) >> 5;
    int nw = gridDim.x * 8;
    float* s_h = s_hall + wl * (EPG * H_DIM);

    float wr0 = mlp_w[(2 * F_IN + D_ATTR) * H_DIM + k0];
    float wr1 = mlp_w[(2 * F_IN + D_ATTR) * H_DIM + k0 + 1];
    float eb0 = edge_b[k0], eb1 = edge_b[k0 + 1];
    float cw0 = coord_w[k0], cw1 = coord_w[k0 + 1];
    float cb = coord_b[0];

    const int NGROUPS = N_EDGES / EPG;             // 50000
    for (int g = warp; g < NGROUPS; g += nw) {
        int ebase = g * EPG;
        int4 sa = *(const int4*)(eidx + ebase);
        int4 sb = *(const int4*)(eidx + ebase + 4);
        int4 da = *(const int4*)(eidx + N_EDGES + ebase);
        int4 db = *(const int4*)(eidx + N_EDGES + ebase + 4);
        int srcs[EPG] = {sa.x, sa.y, sa.z, sa.w, sb.x, sb.y, sb.z, sb.w};
        int dsts[EPG] = {da.x, da.y, da.z, da.w, db.x, db.y, db.z, db.w};
        float mydx = 0.f, mydy = 0.f, mydz = 0.f;

        // ---- phase 1: per-edge h, in 2 batches of 4
#pragma unroll
        for (int half = 0; half < 2; half++) {
            float b0[4], b1[4];
            ull hk0[4], hk1[4];
#pragma unroll
            for (int t = 0; t < 4; t++) {
                int ei = half * 4 + t;
                int src = srcs[ei], dst = dsts[ei];
                float dx = pos[dst * 3 + 0] - pos[src * 3 + 0];
                float dy = pos[dst * 3 + 1] - pos[src * 3 + 1];
                float dz = pos[dst * 3 + 2] - pos[src * 3 + 2];
                if (lane == ei) { mydx = dx; mydy = dy; mydz = dz; }
                float radial = dx * dx + dy * dy + dz * dz;
                float2 av = *(const float2*)(a + (size_t)dst * H_DIM + k0);
                float2 bv = *(const float2*)(b + (size_t)src * H_DIM + k0);
                b0[t] = av.x + bv.x + radial * wr0;
                b1[t] = av.y + bv.y + radial * wr1;
                hk0[t] = 0; hk1[t] = 0;
            }
#pragma unroll
            for (int q = 0; q < 2; q++) {
                ulonglong2 w0 = *(const ulonglong2*)(s_wattrP + (4*q+0)*64 + 2*lane);
                ulonglong2 w1 = *(const ulonglong2*)(s_wattrP + (4*q+1)*64 + 2*lane);
                ulonglong2 w2 = *(const ulonglong2*)(s_wattrP + (4*q+2)*64 + 2*lane);
                ulonglong2 w3 = *(const ulonglong2*)(s_wattrP + (4*q+3)*64 + 2*lane);
#pragma unroll
                for (int t = 0; t < 4; t++) {
                    int e = ebase + half * 4 + t;
                    ulonglong2 eaA = *(const ulonglong2*)(edge_attr + (size_t)e * D_ATTR + 8*q);
                    ulonglong2 eaB = *(const ulonglong2*)(edge_attr + (size_t)e * D_ATTR + 8*q + 4);
                    hk0[t] = fma2(eaA.x, w0.x, hk0[t]); hk1[t] = fma2(eaA.x, w0.y, hk1[t]);
                    hk0[t] = fma2(eaA.y, w1.x, hk0[t]); hk1[t] = fma2(eaA.y, w1.y, hk1[t]);
                    hk0[t] = fma2(eaB.x, w2.x, hk0[t]); hk1[t] = fma2(eaB.x, w2.y, hk1[t]);
                    hk0[t] = fma2(eaB.y, w3.x, hk0[t]); hk1[t] = fma2(eaB.y, w3.y, hk1[t]);
                }
            }
#pragma unroll
            for (int t = 0; t < 4; t++) {
                float2 v0 = unpack2(hk0[t]), v1 = unpack2(hk1[t]);
                float h0 = silu_f(b0[t] + v0.x + v0.y);
                float h1 = silu_f(b1[t] + v1.x + v1.y);
                *(float2*)(s_h + (half * 4 + t) * H_DIM + k0) = make_float2(h0, h1);
            }
        }
        __syncwarp();

        // ---- phase 2: e = silu(h @ edge_w + eb), k-packed
        ull acc0[EPG], acc1[EPG];
#pragma unroll
        for (int t = 0; t < EPG; t++) { acc0[t] = 0; acc1[t] = 0; }
#pragma unroll 4
        for (int q = 0; q < 16; q++) {
            ulonglong2 wA = *(const ulonglong2*)(s_wp + (2*q)   * 64 + 2*lane);
            ulonglong2 wB = *(const ulonglong2*)(s_wp + (2*q+1) * 64 + 2*lane);
#pragma unroll
            for (int t = 0; t < EPG; t++) {
                ulonglong2 hv = *(const ulonglong2*)(s_h + t * H_DIM + 4 * q);
                acc0[t] = fma2(hv.x, wA.x, acc0[t]); acc1[t] = fma2(hv.x, wA.y, acc1[t]);
                acc0[t] = fma2(hv.y, wB.x, acc0[t]); acc1[t] = fma2(hv.y, wB.y, acc1[t]);
            }
        }
        __syncwarp();

        // ---- epilogue
        float myss = 0.f;
#pragma unroll
        for (int t = 0; t < EPG; t++) {
            float2 v0 = unpack2(acc0[t]), v1 = unpack2(acc1[t]);
            float e0 = silu_f(eb0 + v0.x + v0.y);
            float e1 = silu_f(eb1 + v1.x + v1.y);
            red_add_v2(eagg + (size_t)dsts[t] * H_DIM + k0, e0, e1);
            if (do_coord) {
                float p = e0 * cw0 + e1 * cw1;
                p += __shfl_xor_sync(0xffffffffu, p, 16);
                p += __shfl_xor_sync(0xffffffffu, p, 8);
                p += __shfl_xor_sync(0xffffffffu, p, 4);
                p += __shfl_xor_sync(0xffffffffu, p, 2);
                p += __shfl_xor_sync(0xffffffffu, p, 1);
                if (lane == t) myss = silu_f(p + cb);
            }
        }
        if (do_coord && lane < EPG) {
            int d3 = dsts[lane] * 3;
            atomicAdd(cusum + d3 + 0, mydx * myss);
            atomicAdd(cusum + d3 + 1, mydy * myss);
            atomicAdd(cusum + d3 + 2, mydz * myss);
            atomicAdd(deg + dsts[lane], 1.0f);
        }
    }
}

// ---------------- node1 layer 0: t = silu([x,eagg]@w1 + b1), 8 nodes/warp -----
__global__ void __launch_bounds__(256, 3) node1_kernel(const float* __restrict__ xin,
                                                       const float* __restrict__ eagg,
                                                       const float* __restrict__ nw1,
                                                       const float* __restrict__ nb1,
                                                       float* __restrict__ tout) {
    extern __shared__ ull s_w1p[];                 // 6144 ull = 48KB
    for (int i = threadIdx.x; i < 96 * 64; i += 256) {
        int kp = i >> 6, c = i & 63;
        s_w1p[i] = pack2(nw1[(2 * kp) * H_DIM + c], nw1[(2 * kp + 1) * H_DIM + c]);
    }
    __syncthreads();

    int lane = threadIdx.x & 31;
    int warp = (blockIdx.x * 256 + threadIdx.x) >> 5;
    int nw = gridDim.x * 8;
    float nb0 = nb1[2 * lane], nbx1 = nb1[2 * lane + 1];
    const int NG = N_NODES / 8;                    // 3125

    for (int g = warp; g < NG; g += nw) {
        int nbase = g * 8;
        ull a0[8], a1[8];
#pragma unroll
        for (int t = 0; t < 8; t++) { a0[t] = 0; a1[t] = 0; }
#pragma unroll 4
        for (int q = 0; q < 32; q++) {
            ulonglong2 w0 = *(const ulonglong2*)(s_w1p + (2*q)   * 64 + 2*lane);
            ulonglong2 w1 = *(const ulonglong2*)(s_w1p + (2*q+1) * 64 + 2*lane);
#pragma unroll
            for (int t = 0; t < 8; t++) {
                ulonglong2 xp = *(const ulonglong2*)(xin + (size_t)(nbase + t) * F_IN + 4 * q);
                a0[t] = fma2(xp.x, w0.x, a0[t]); a1[t] = fma2(xp.x, w0.y, a1[t]);
                a0[t] = fma2(xp.y, w1.x, a0[t]); a1[t] = fma2(xp.y, w1.y, a1[t]);
            }
        }
#pragma unroll 4
        for (int q = 0; q < 16; q++) {
            ulonglong2 w0 = *(const ulonglong2*)(s_w1p + (64 + 2*q)     * 64 + 2*lane);
            ulonglong2 w1 = *(const ulonglong2*)(s_w1p + (64 + 2*q + 1) * 64 + 2*lane);
#pragma unroll
            for (int t = 0; t < 8; t++) {
                ulonglong2 ep = *(const ulonglong2*)(eagg + (size_t)(nbase + t) * H_DIM + 4 * q);
                a0[t] = fma2(ep.x, w0.x, a0[t]); a1[t] = fma2(ep.x, w0.y, a1[t]);
                a0[t] = fma2(ep.y, w1.x, a0[t]); a1[t] = fma2(ep.y, w1.y, a1[t]);
            }
        }
#pragma unroll
        for (int t = 0; t < 8; t++) {
            float2 v0 = unpack2(a0[t]), v1 = unpack2(a1[t]);
            *(float2*)(tout + (size_t)(nbase + t) * H_DIM + 2*lane) =
                make_float2(silu_f(nb0 + v0.x + v0.y), silu_f(nbx1 + v1.x + v1.y));
        }
    }
}

// ---------------- node1 layer 1 (folded): t1 = silu(t@Wnx + eagg@W1e + bias) --
__global__ void __launch_bounds__(256, 3) node1_l1_kernel(const float* __restrict__ tin,
                                                          const float* __restrict__ eagg,
                                                          const float* __restrict__ fold,
                                                          const float* __restrict__ nw1_1,
                                                          const float* __restrict__ nb1_1,
                                                          float* __restrict__ tout) {
    extern __shared__ ull swp[];                   // 4096 ull = 32KB: Wnx | W1e kpacked
    for (int i = threadIdx.x; i < 2048; i += 256) {
        int kp = i >> 6, c = i & 63;
        swp[i]        = pack2(fold[(130 + 2 * kp) * H_DIM + c],
                              fold[(130 + 2 * kp + 1) * H_DIM + c]);
        swp[2048 + i] = pack2(nw1_1[(128 + 2 * kp) * H_DIM + c],
                              nw1_1[(128 + 2 * kp + 1) * H_DIM + c]);
    }
    __syncthreads();

    int lane = threadIdx.x & 31;
    int warp = (blockIdx.x * 256 + threadIdx.x) >> 5;
    int nw = gridDim.x * 8;
    float bn0 = fold[(130 + 64) * H_DIM + 2*lane]     + nb1_1[2*lane];
    float bn1 = fold[(130 + 64) * H_DIM + 2*lane + 1] + nb1_1[2*lane + 1];
    const int NG = N_NODES / 8;

    for (int g = warp; g < NG; g += nw) {
        int nbase = g * 8;
        ull a0[8], a1[8];
#pragma unroll
        for (int t = 0; t < 8; t++) { a0[t] = 0; a1[t] = 0; }
#pragma unroll 4
        for (int q = 0; q < 16; q++) {             // t part (K=64)
            ulonglong2 w0 = *(const ulonglong2*)(swp + (2*q)   * 64 + 2*lane);
            ulonglong2 w1 = *(const ulonglong2*)(swp + (2*q+1) * 64 + 2*lane);
#pragma unroll
            for (int t = 0; t < 8; t++) {
                ulonglong2 tp = *(const ulonglong2*)(tin + (size_t)(nbase + t) * H_DIM + 4 * q);
                a0[t] = fma2(tp.x, w0.x, a0[t]); a1[t] = fma2(tp.x, w0.y, a1[t]);
                a0[t] = fma2(tp.y, w1.x, a0[t]); a1[t] = fma2(tp.y, w1.y, a1[t]);
            }
        }
#pragma unroll 4
        for (int q = 0; q < 16; q++) {             // eagg part (K=64)
            ulonglong2 w0 = *(const ulonglong2*)(swp + 2048 + (2*q)   * 64 + 2*lane);
            ulonglong2 w1 = *(const ulonglong2*)(swp + 2048 + (2*q+1) * 64 + 2*lane);
#pragma unroll
            for (int t = 0; t < 8; t++) {
                ulonglong2 ep = *(const ulonglong2*)(eagg + (size_t)(nbase + t) * H_DIM + 4 * q);
                a0[t] = fma2(ep.x, w0.x, a0[t]); a1[t] = fma2(ep.x, w0.y, a1[t]);
                a0[t] = fma2(ep.y, w1.x, a0[t]); a1[t] = fma2(ep.y, w1.y, a1[t]);
            }
        }
#pragma unroll
        for (int t = 0; t < 8; t++) {
            float2 v0 = unpack2(a0[t]), v1 = unpack2(a1[t]);
            *(float2*)(tout + (size_t)(nbase + t) * H_DIM + 2*lane) =
                make_float2(silu_f(bn0 + v0.x + v0.y), silu_f(bn1 + v1.x + v1.y));
        }
    }
}

// ---------------- pooling of t1 (H=64), batch sorted ---------------------------
__global__ void pool_kernel(const float* __restrict__ t,
                            const int* __restrict__ batch,
                            float* __restrict__ gsum, float* __restrict__ gcnt) {
    int lane = threadIdx.x & 31;
    int warp = (blockIdx.x * blockDim.x + threadIdx.x) >> 5;
    int nw = (gridDim.x * blockDim.x) >> 5;
    int nchunks = (N_NODES + 7) / 8;

    for (int c = warp; c < nchunks; c += nw) {
        int base = c * 8;
        float2 acc = make_float2(0.f, 0.f);
        int curb = batch[base];
        float cnt = 0.f;
        for (int i = 0; i < 8; i++) {
            int node = base + i;
            if (node >= N_NODES) break;
            int bb = batch[node];
            if (bb != curb) {
                red_add_v2(gsum + curb * H_DIM + 2 * lane, acc.x, acc.y);
                if (lane == 0) atomicAdd(&gcnt[curb], cnt);
                acc = make_float2(0.f, 0.f);
                cnt = 0.f;
                curb = bb;
            }
            float2 v = *(const float2*)(t + (size_t)node * H_DIM + 2 * lane);
            acc.x += v.x; acc.y += v.y;
            cnt += 1.f;
        }
        red_add_v2(gsum + curb * H_DIM + 2 * lane, acc.x, acc.y);
        if (lane == 0) atomicAdd(&gcnt[curb], cnt);
    }
}

// ---------------- final: fold layer1 w2 + output MLP ---------------------------
__global__ void final_kernel(const float* __restrict__ gsum,
                             const float* __restrict__ gcnt,
                             const float* __restrict__ nw2,   // (64,128) layer1
                             const float* __restrict__ nb2,   // (128,)
                             const float* __restrict__ w1,
                             const float* __restrict__ b1,
                             const float* __restrict__ w2,
                             const float* __restrict__ b2,
                             float* __restrict__ out) {
    int g = blockIdx.x;
    int tx = threadIdx.x;  // 128 threads
    __shared__ float sm64[H_DIM];
    __shared__ float sg[HID];
    __shared__ float st[HID];
    float cnt = fmaxf(gcnt[g], 1.0f);
    if (tx < H_DIM) sm64[tx] = gsum[g * H_DIM + tx] / cnt;
    __syncthreads();
    float gv = nb2[tx];
#pragma unroll 8
    for (int k = 0; k < H_DIM; k++) gv += sm64[k] * nw2[k * HID + tx];
    sg[tx] = fmaxf(gv, 0.0f);
    __syncthreads();
    float acc = b1[tx];
#pragma unroll 8
    for (int j = 0; j < HID; j++) acc += sg[j] * w1[j * HID + tx];
    st[tx] = fmaxf(acc, 0.0f);
    __syncthreads();
    if (tx < OUT_DIM) {
        float o = b2[tx];
#pragma unroll 8
        for (int k = 0; k < HID; k++) o += st[k] * w2[k * OUT_DIM + tx];
        out[g * OUT_DIM + tx] = o;
    }
}

// ---------------- launch --------------------------------------------------------
extern "C" void kernel_launch(void* const* d_in, const int* in_sizes, int n_in,
                              void* d_out, int out_size) {
    const float* x         = (const float*)d_in[0];
    const float* pos       = (const float*)d_in[1];
    const float* edge_attr = (const float*)d_in[2];
    const int* eidx        = (const int*)d_in[3];
    const int* batch       = (const int*)d_in[4];

    const float* mlp_w[2]  = {(const float*)d_in[5],  (const float*)d_in[14]};
    const float* edge_w[2] = {(const float*)d_in[6],  (const float*)d_in[15]};
    const float* edge_b[2] = {(const float*)d_in[7],  (const float*)d_in[16]};
    const float* coord_w[2]= {(const float*)d_in[8],  (const float*)d_in[17]};
    const float* coord_b[2]= {(const float*)d_in[9],  (const float*)d_in[18]};
    const float* nw1[2]    = {(const float*)d_in[10], (const float*)d_in[19]};
    const float* nb1[2]    = {(const float*)d_in[11], (const float*)d_in[20]};
    const float* nw2[2]    = {(const float*)d_in[12], (const float*)d_in[21]};
    const float* nb2[2]    = {(const float*)d_in[13], (const float*)d_in[22]};
    const float* ow1 = (const float*)d_in[23];
    const float* ob1 = (const float*)d_in[24];
    const float* ow2 = (const float*)d_in[25];
    const float* ob2 = (const float*)d_in[26];
    float* out = (float*)d_out;

    float *pa, *pb, *pe, *pt, *pt2, *pc, *pd, *ppos, *pgs, *pgc, *pf;
    cudaGetSymbolAddress((void**)&pa, g_a);
    cudaGetSymbolAddress((void**)&pb, g_b);
    cudaGetSymbolAddress((void**)&pe, g_eagg);
    cudaGetSymbolAddress((void**)&pt, g_t);
    cudaGetSymbolAddress((void**)&pt2, g_t2);
    cudaGetSymbolAddress((void**)&pc, g_cusum);
    cudaGetSymbolAddress((void**)&pd, g_deg);
    cudaGetSymbolAddress((void**)&ppos, g_pos1);
    cudaGetSymbolAddress((void**)&pgs, g_gsum);
    cudaGetSymbolAddress((void**)&pgc, g_gcnt);
    cudaGetSymbolAddress((void**)&pf, g_fold);

    const int PRE_SMEM  = 8192 * (int)sizeof(ull);                         // 64KB
    const int PRT_SMEM  = 4096 * (int)sizeof(ull);                         // 32KB
    const int N1_SMEM   = 96 * 64 * (int)sizeof(ull);                      // 48KB
    const int N1L1_SMEM = 4096 * (int)sizeof(ull);                         // 32KB
    const int EDGE_SMEM = 2560 * (int)sizeof(ull) + 8 * EPG * H_DIM * (int)sizeof(float); // 36KB
    cudaFuncSetAttribute(precompute_ab, cudaFuncAttributeMaxDynamicSharedMemorySize, PRE_SMEM);
    cudaFuncSetAttribute(precompute_t, cudaFuncAttributeMaxDynamicSharedMemorySize, PRT_SMEM);
    cudaFuncSetAttribute(node1_kernel, cudaFuncAttributeMaxDynamicSharedMemorySize, N1_SMEM);
    cudaFuncSetAttribute(node1_l1_kernel, cudaFuncAttributeMaxDynamicSharedMemorySize, N1L1_SMEM);
    cudaFuncSetAttribute(edge_kernel, cudaFuncAttributeMaxDynamicSharedMemorySize, EDGE_SMEM);

    // folded weights (no data deps other than weight inputs)
    prep_fold<<<dim3(65, 3), 64>>>(nw2[0], nb2[0], mlp_w[1], nw1[1], pf);

    // ---------------- layer 0
    cudaMemsetAsync(pe, 0, (size_t)N_NODES * H_DIM * sizeof(float));
    cudaMemsetAsync(pc, 0, (size_t)N_NODES * 3 * sizeof(float));
    cudaMemsetAsync(pd, 0, (size_t)N_NODES * sizeof(float));
    precompute_ab<<<444, 256, PRE_SMEM>>>(x, mlp_w[0], pa, pb);
    edge_kernel<<<444, 256, EDGE_SMEM>>>(pos, eidx, edge_attr, mlp_w[0],
                                         edge_w[0], edge_b[0], coord_w[0], coord_b[0],
                                         pa, pb, pe, pc, pd, 1);
    node1_kernel<<<444, 256, N1_SMEM>>>(x, pe, nw1[0], nb1[0], pt);

    // ---------------- layer 1 (x1 folded away)
    cudaMemsetAsync(pe, 0, (size_t)N_NODES * H_DIM * sizeof(float));
    precompute_t<<<444, 256, PRT_SMEM>>>(pt, pf, pos, pc, pd, pa, pb, ppos);
    edge_kernel<<<444, 256, EDGE_SMEM>>>(ppos, eidx, edge_attr, mlp_w[1],
                                         edge_w[1], edge_b[1], coord_w[1], coord_b[1],
                                         pa, pb, pe, pc, pd, 0);
    node1_l1_kernel<<<444, 256, N1L1_SMEM>>>(pt, pe, pf, nw1[1], nb1[1], pt2);

    // ---------------- pooling + output
    cudaMemsetAsync(pgs, 0, (size_t)G_GRAPHS * H_DIM * sizeof(float));
    cudaMemsetAsync(pgc, 0, (size_t)G_GRAPHS * sizeof(float));
    pool_kernel<<<64, 256>>>(pt2, batch, pgs, pgc);
    final_kernel<<<G_GRAPHS, HID>>>(pgs, pgc, nw2[1], nb2[1], ow1, ob1, ow2, ob2, out);
}